// round 10
// baseline (speedup 1.0000x reference)
#include <cuda_runtime.h>
#include <cstdint>

#define Bv   4
#define Nv   512
#define Dv   128
#define Hv   8
#define FFv  512
#define ROWS (Bv*Nv)
#define P1_NT 8192              // e tiles of 128 rows

__device__ float g_hn [ROWS*Dv];
__device__ float g_qkv[ROWS*3*Dv];
__device__ float g_y  [ROWS*Dv];
__device__ float g_z  [ROWS*Dv];
__device__ float g_hid[ROWS*FFv];
__device__ float g_e12[(size_t)ROWS*Nv*16];   // 64 MB [b,i,j][h*2+{e1,e2}]

__device__ __forceinline__ void cpa16(void* s, const void* g) {
    unsigned sa = (unsigned)__cvta_generic_to_shared(s);
    asm volatile("cp.async.cg.shared.global [%0], [%1], 16;" :: "r"(sa), "l"(g));
}
__device__ __forceinline__ void cp_commit() { asm volatile("cp.async.commit_group;"); }
__device__ __forceinline__ void cp_wait1()  { asm volatile("cp.async.wait_group 1;" ::: "memory"); }
__device__ __forceinline__ unsigned cvt_tf32(float x) {
    unsigned u; asm("cvt.rna.tf32.f32 %0, %1;" : "=r"(u) : "f"(x)); return u;
}
__device__ __forceinline__ void mma_tf32(float c[4], const unsigned a[4],
                                         unsigned b0, unsigned b1) {
    asm volatile("mma.sync.aligned.m16n8k8.row.col.f32.tf32.tf32.f32 "
                 "{%0,%1,%2,%3},{%4,%5,%6,%7},{%8,%9},{%0,%1,%2,%3};"
                 : "+f"(c[0]), "+f"(c[1]), "+f"(c[2]), "+f"(c[3])
                 : "r"(a[0]), "r"(a[1]), "r"(a[2]), "r"(a[3]), "r"(b0), "r"(b1));
}
__device__ __forceinline__ float dot16(const float4 q[4], const float4* kr) {
    float4 k0 = kr[0], k1 = kr[1], k2 = kr[2], k3 = kr[3];
    float d = q[0].x*k0.x;
    d = fmaf(q[0].y, k0.y, d); d = fmaf(q[0].z, k0.z, d); d = fmaf(q[0].w, k0.w, d);
    d = fmaf(q[1].x, k1.x, d); d = fmaf(q[1].y, k1.y, d);
    d = fmaf(q[1].z, k1.z, d); d = fmaf(q[1].w, k1.w, d);
    d = fmaf(q[2].x, k2.x, d); d = fmaf(q[2].y, k2.y, d);
    d = fmaf(q[2].z, k2.z, d); d = fmaf(q[2].w, k2.w, d);
    d = fmaf(q[3].x, k3.x, d); d = fmaf(q[3].y, k3.y, d);
    d = fmaf(q[3].z, k3.z, d); d = fmaf(q[3].w, k3.w, d);
    return d;
}

// ---------------- rmsnorm ---------------------------------------------------
__global__ void rmsnorm_k(const float* __restrict__ x, const float* __restrict__ add,
                          const float* __restrict__ w, float* __restrict__ out) {
    int row  = blockIdx.x * 8 + (threadIdx.x >> 5);
    int lane = threadIdx.x & 31;
    float4 v = ((const float4*)(x + (size_t)row*Dv))[lane];
    if (add) {
        float4 a = ((const float4*)(add + (size_t)row*Dv))[lane];
        v.x += a.x; v.y += a.y; v.z += a.z; v.w += a.w;
    }
    float ss = v.x*v.x + v.y*v.y + v.z*v.z + v.w*v.w;
    #pragma unroll
    for (int off = 16; off; off >>= 1) ss += __shfl_xor_sync(0xffffffffu, ss, off);
    float s = rsqrtf(ss * (1.0f/Dv) + 1e-5f);
    float4 wv = ((const float4*)w)[lane];
    ((float4*)(out + (size_t)row*Dv))[lane] =
        make_float4(v.x*s*wv.x, v.y*s*wv.y, v.z*s*wv.z, v.w*s*wv.w);
}

// ---------------- tiled GEMM 64x64 ------------------------------------------
template<bool GELU, bool ADDC>
__global__ void gemm64(const float* __restrict__ A, const float* __restrict__ B,
                       const float* __restrict__ Cadd, float* __restrict__ C,
                       int M, int Nn, int K) {
    __shared__ float Ast[32*64];
    __shared__ float Bs [32*64];
    int tid = threadIdx.x;
    int bm = blockIdx.y, bn = blockIdx.x;
    int tx = tid & 15, ty = tid >> 4;
    float acc[4][4] = {};
    for (int k0 = 0; k0 < K; k0 += 32) {
        for (int u = tid; u < 512; u += 256) {
            int r = u >> 3, c4 = u & 7;
            float4 a = *(const float4*)&A[(size_t)(bm*64 + r)*K + k0 + c4*4];
            Ast[(c4*4+0)*64 + r] = a.x; Ast[(c4*4+1)*64 + r] = a.y;
            Ast[(c4*4+2)*64 + r] = a.z; Ast[(c4*4+3)*64 + r] = a.w;
        }
        for (int u = tid; u < 512; u += 256) {
            int kk = u >> 4, n4 = u & 15;
            *(float4*)&Bs[kk*64 + n4*4] =
                *(const float4*)&B[(size_t)(k0+kk)*Nn + bn*64 + n4*4];
        }
        __syncthreads();
        #pragma unroll
        for (int kk = 0; kk < 32; kk++) {
            float4 a4 = *(const float4*)&Ast[kk*64 + ty*4];
            float4 b4 = *(const float4*)&Bs [kk*64 + tx*4];
            float av[4] = {a4.x, a4.y, a4.z, a4.w};
            float bv[4] = {b4.x, b4.y, b4.z, b4.w};
            #pragma unroll
            for (int i = 0; i < 4; i++)
                #pragma unroll
                for (int j = 0; j < 4; j++)
                    acc[i][j] = fmaf(av[i], bv[j], acc[i][j]);
        }
        __syncthreads();
    }
    #pragma unroll
    for (int i = 0; i < 4; i++) {
        int r = bm*64 + ty*4 + i;
        #pragma unroll
        for (int j = 0; j < 4; j++) {
            int c = bn*64 + tx*4 + j;
            float v = acc[i][j];
            if (GELU) v = 0.5f * v * (1.0f + erff(v * 0.70710678118654752f));
            if (ADDC) v += Cadd[(size_t)r*Nn + c];
            C[(size_t)r*Nn + c] = v;
        }
    }
}

// ---------------- PASS 1: e12 = e @ W_e (tf32 mma, A direct from LDG) -------
__global__ void __launch_bounds__(256) eproj2_k(
    const float* __restrict__ e, const float* __restrict__ We,
    float* __restrict__ e12)
{
    __shared__ float2 sbhi[16*2*32];
    __shared__ float2 sblo[16*2*32];
    const int tid = threadIdx.x;
    const int warp = tid >> 5, lane = tid & 31;
    const int g = lane >> 2, t = lane & 3;

    if (warp == 0) {
        #pragma unroll
        for (int kk = 0; kk < 16; kk++) {
            int kkp = kk >> 1, s = kk & 1;
            int c0 = kkp*16 + 4*t + 2*s;
            #pragma unroll
            for (int nt = 0; nt < 2; nt++) {
                int n = nt*8 + g;
                int wcol = (n & 1)*Hv + (n >> 1);
                float w0 = We[c0*16 + wcol], w1 = We[(c0+1)*16 + wcol];
                unsigned h0 = cvt_tf32(w0), h1 = cvt_tf32(w1);
                sbhi[(kk*2+nt)*32 + lane] =
                    make_float2(__uint_as_float(h0), __uint_as_float(h1));
                sblo[(kk*2+nt)*32 + lane] = make_float2(
                    __uint_as_float(cvt_tf32(w0 - __uint_as_float(h0))),
                    __uint_as_float(cvt_tf32(w1 - __uint_as_float(h1))));
            }
        }
    }
    __syncthreads();

    for (int tile = blockIdx.x; tile < P1_NT; tile += gridDim.x) {
        const float4* A = (const float4*)(e + ((size_t)tile*128 + warp*16)*Dv);
        float c[2][4] = {};
        #pragma unroll
        for (int kkp = 0; kkp < 8; kkp++) {
            float4 alo = A[(size_t) g    *32 + kkp*4 + t];
            float4 ahi = A[(size_t)(g+8)*32 + kkp*4 + t];
            #pragma unroll
            for (int s = 0; s < 2; s++) {
                int kk = kkp*2 + s;
                float a0f = s ? alo.z : alo.x;
                float a1f = s ? ahi.z : ahi.x;
                float a2f = s ? alo.w : alo.y;
                float a3f = s ? ahi.w : ahi.y;
                unsigned ah[4] = {cvt_tf32(a0f), cvt_tf32(a1f),
                                  cvt_tf32(a2f), cvt_tf32(a3f)};
                unsigned al[4] = {
                    cvt_tf32(a0f - __uint_as_float(ah[0])),
                    cvt_tf32(a1f - __uint_as_float(ah[1])),
                    cvt_tf32(a2f - __uint_as_float(ah[2])),
                    cvt_tf32(a3f - __uint_as_float(ah[3]))};
                #pragma unroll
                for (int nt = 0; nt < 2; nt++) {
                    float2 bh = sbhi[(kk*2+nt)*32 + lane];
                    float2 bl = sblo[(kk*2+nt)*32 + lane];
                    unsigned b0 = __float_as_uint(bh.x), b1 = __float_as_uint(bh.y);
                    mma_tf32(c[nt], ah, b0, b1);
                    mma_tf32(c[nt], al, b0, b1);
                    mma_tf32(c[nt], ah, __float_as_uint(bl.x), __float_as_uint(bl.y));
                }
            }
        }
        float* out = e12 + ((size_t)tile*128 + warp*16)*16;
        #pragma unroll
        for (int nt = 0; nt < 2; nt++) {
            *(float2*)&out[ g    *16 + nt*8 + 2*t] = make_float2(c[nt][0], c[nt][1]);
            *(float2*)&out[(g+8)*16 + nt*8 + 2*t] = make_float2(c[nt][2], c[nt][3]);
        }
    }
}

// ---------------- PASS 2: attention, 2 i rows & full head frag per thread ---
// block = (b, 16 i), 512 thr; warp w: ip=w&7 (i-pair), jh=w>>3 (j half);
// lane: hh=lane>>2, jp=lane&3. Tiles hold 64 j (32 per half), double-buffered.
#define ATTN_SMEM (2*2*64*128*4)   // 128 KB

__global__ void __launch_bounds__(512, 1) attn4_k(
    const float* __restrict__ qkv, const float* __restrict__ e12,
    float* __restrict__ yout)
{
    extern __shared__ float sm[];
    float* ks = sm;                // [2][64][128]
    float* vs = sm + 2*64*128;

    const int tid = threadIdx.x;
    const int b  = blockIdx.x >> 5;
    const int i0 = (blockIdx.x & 31) * 16;
    const int w = tid >> 5, lane = tid & 31;
    const int ip = w & 7, jh = w >> 3;
    const int hh = lane >> 2, jp = lane & 3;
    const int ia = i0 + ip*2, ib = ia + 1;

    float4 qa[4], qb[4];
    #pragma unroll
    for (int u = 0; u < 4; u++) {
        float4 q = *(const float4*)(qkv + (size_t)(b*Nv + ia)*384 + hh*16 + u*4);
        qa[u] = make_float4(q.x*0.25f, q.y*0.25f, q.z*0.25f, q.w*0.25f);
        q = *(const float4*)(qkv + (size_t)(b*Nv + ib)*384 + hh*16 + u*4);
        qb[u] = make_float4(q.x*0.25f, q.y*0.25f, q.z*0.25f, q.w*0.25f);
    }

    auto load_tile = [&](int t, int par) {
        #pragma unroll
        for (int ph = 0; ph < 4; ph++) {
            int u = tid + ph*512;          // 2048 slots: r 0..63, x4 0..31
            int r = u >> 5, x4 = u & 31;
            int jg = (r < 32) ? (t*32 + r) : (256 + t*32 + (r - 32));
            const float* src = qkv + (size_t)(b*Nv + jg)*384 + 128 + x4*4;
            cpa16(ks + par*8192 + r*128 + x4*4, src);
            cpa16(vs + par*8192 + r*128 + x4*4, src + 128);
        }
    };

    float4 aA[4] = {}, aB[4] = {};
    float dA = 0.f, dB = 0.f;

    load_tile(0, 0);
    cp_commit();
    for (int t = 0; t < 8; t++) {
        int par = t & 1;
        if (t + 1 < 8) load_tile(t + 1, par ^ 1);
        cp_commit();
        cp_wait1();
        __syncthreads();

        const float* kt = ks + par*8192 + jh*32*128;
        const float* vt = vs + par*8192 + jh*32*128;
        const float* eA = e12 + ((size_t)(b*Nv + ia)*Nv + jh*256 + t*32)*16 + hh*2;
        const float* eB = eA + (size_t)Nv*16;
        #pragma unroll
        for (int jj = 0; jj < 8; jj++) {
            int l = jj*4 + jp;
            const float4* kr = (const float4*)(kt + l*128 + hh*16);
            float da = dot16(qa, kr);
            float db = dot16(qb, kr);
            float2 eea = *(const float2*)(eA + l*16);
            float2 eeb = *(const float2*)(eB + l*16);
            float pa = __expf(da + eea.x);
            float pb = __expf(db + eeb.x);
            dA += pa; dB += pb;
            pa *= eea.y; pb *= eeb.y;
            const float4* vr = (const float4*)(vt + l*128 + hh*16);
            #pragma unroll
            for (int u = 0; u < 4; u++) {
                float4 vv = vr[u];
                aA[u].x = fmaf(pa, vv.x, aA[u].x);
                aA[u].y = fmaf(pa, vv.y, aA[u].y);
                aA[u].z = fmaf(pa, vv.z, aA[u].z);
                aA[u].w = fmaf(pa, vv.w, aA[u].w);
                aB[u].x = fmaf(pb, vv.x, aB[u].x);
                aB[u].y = fmaf(pb, vv.y, aB[u].y);
                aB[u].z = fmaf(pb, vv.z, aB[u].z);
                aB[u].w = fmaf(pb, vv.w, aB[u].w);
            }
        }
        __syncthreads();
    }

    // reduce over jp (lanes 0..3 within quad)
    #pragma unroll
    for (int s = 1; s <= 2; s <<= 1) {
        dA += __shfl_xor_sync(0xffffffffu, dA, s);
        dB += __shfl_xor_sync(0xffffffffu, dB, s);
        #pragma unroll
        for (int u = 0; u < 4; u++) {
            aA[u].x += __shfl_xor_sync(0xffffffffu, aA[u].x, s);
            aA[u].y += __shfl_xor_sync(0xffffffffu, aA[u].y, s);
            aA[u].z += __shfl_xor_sync(0xffffffffu, aA[u].z, s);
            aA[u].w += __shfl_xor_sync(0xffffffffu, aA[u].w, s);
            aB[u].x += __shfl_xor_sync(0xffffffffu, aB[u].x, s);
            aB[u].y += __shfl_xor_sync(0xffffffffu, aB[u].y, s);
            aB[u].z += __shfl_xor_sync(0xffffffffu, aB[u].z, s);
            aB[u].w += __shfl_xor_sync(0xffffffffu, aB[u].w, s);
        }
    }

    // exchange between j-halves via smem (reuse ks region).
    // float4 payload: [row 0..15][hh 0..7] * 16-float stride (64B aligned).
    // denominators in separate scalar array after payload (2048 floats).
    float* xb = sm;
    float* xd = sm + 16*8*16;
    __syncthreads();
    if (jh == 1) {
        float* pa = xb + ((ip*2 + 0)*8 + hh)*16;
        float* pb = xb + ((ip*2 + 1)*8 + hh)*16;
        *(float4*)(pa + jp*4) = aA[jp];
        *(float4*)(pb + jp*4) = aB[jp];
        if (jp == 0) {
            xd[(ip*2 + 0)*8 + hh] = dA;
            xd[(ip*2 + 1)*8 + hh] = dB;
        }
    }
    __syncthreads();
    if (jh == 0) {
        const float* pa = xb + ((ip*2 + 0)*8 + hh)*16;
        const float* pb = xb + ((ip*2 + 1)*8 + hh)*16;
        float4 oa = *(const float4*)(pa + jp*4);
        float4 ob = *(const float4*)(pb + jp*4);
        float invA = 1.0f / (dA + xd[(ip*2 + 0)*8 + hh]);
        float invB = 1.0f / (dB + xd[(ip*2 + 1)*8 + hh]);
        float4 ra = make_float4((aA[jp].x + oa.x)*invA, (aA[jp].y + oa.y)*invA,
                                (aA[jp].z + oa.z)*invA, (aA[jp].w + oa.w)*invA);
        float4 rb = make_float4((aB[jp].x + ob.x)*invB, (aB[jp].y + ob.y)*invB,
                                (aB[jp].z + ob.z)*invB, (aB[jp].w + ob.w)*invB);
        *(float4*)(yout + (size_t)(b*Nv + ia)*Dv + hh*16 + jp*4) = ra;
        *(float4*)(yout + (size_t)(b*Nv + ib)*Dv + hh*16 + jp*4) = rb;
    }
}

// ---------------- host launch ----------------------------------------------
extern "C" void kernel_launch(void* const* d_in, const int* in_sizes, int n_in,
                              void* d_out, int out_size) {
    const float* h    = (const float*)d_in[0];
    const float* e    = (const float*)d_in[1];
    const float* W_h  = (const float*)d_in[2];
    const float* W_e  = (const float*)d_in[3];
    const float* n1   = (const float*)d_in[4];
    const float* n2   = (const float*)d_in[5];
    const float* W_fc = (const float*)d_in[6];
    const float* W_pr = (const float*)d_in[7];
    float* out = (float*)d_out;

    float *p_hn, *p_qkv, *p_y, *p_z, *p_hid, *p_e12;
    cudaGetSymbolAddress((void**)&p_hn,  g_hn);
    cudaGetSymbolAddress((void**)&p_qkv, g_qkv);
    cudaGetSymbolAddress((void**)&p_y,   g_y);
    cudaGetSymbolAddress((void**)&p_z,   g_z);
    cudaGetSymbolAddress((void**)&p_hid, g_hid);
    cudaGetSymbolAddress((void**)&p_e12, g_e12);

    cudaFuncSetAttribute(attn4_k, cudaFuncAttributeMaxDynamicSharedMemorySize,
                         ATTN_SMEM);

    rmsnorm_k<<<ROWS/8, 256>>>(h, nullptr, n1, p_hn);
    gemm64<false,false><<<dim3(384/64, ROWS/64), 256>>>(p_hn, W_h, nullptr, p_qkv,
                                                        ROWS, 3*Dv, Dv);
    eproj2_k<<<592, 256>>>(e, W_e, p_e12);
    attn4_k<<<Bv*(Nv/16), 512, ATTN_SMEM>>>(p_qkv, p_e12, p_y);
    rmsnorm_k<<<ROWS/8, 256>>>(p_y, h, n2, p_z);
    gemm64<true,false><<<dim3(FFv/64, ROWS/64), 256>>>(p_z, W_fc, nullptr, p_hid,
                                                       ROWS, FFv, Dv);
    gemm64<false,true><<<dim3(Dv/64, ROWS/64), 256>>>(p_hid, W_pr, p_y, out,
                                                      ROWS, Dv, FFv);
}

// round 11
// speedup vs baseline: 1.7664x; 1.7664x over previous
#include <cuda_runtime.h>
#include <cstdint>

#define Bv   4
#define Nv   512
#define Dv   128
#define Hv   8
#define FFv  512
#define ROWS (Bv*Nv)
#define P1_NT 8192              // e tiles of 128 rows
#define KSTR 132                // padded k/v smem row stride (floats)

__device__ float g_hn [ROWS*Dv];
__device__ float g_qkv[ROWS*3*Dv];
__device__ float g_y  [ROWS*Dv];
__device__ float g_z  [ROWS*Dv];
__device__ float g_hid[ROWS*FFv];
__device__ float g_e12[(size_t)ROWS*Nv*16];   // 64 MB [b,i,j][h*2+{e1,e2}]

__device__ __forceinline__ void cpa16(void* s, const void* g) {
    unsigned sa = (unsigned)__cvta_generic_to_shared(s);
    asm volatile("cp.async.cg.shared.global [%0], [%1], 16;" :: "r"(sa), "l"(g));
}
__device__ __forceinline__ void cp_commit() { asm volatile("cp.async.commit_group;"); }
__device__ __forceinline__ void cp_wait1()  { asm volatile("cp.async.wait_group 1;" ::: "memory"); }
__device__ __forceinline__ unsigned cvt_tf32(float x) {
    unsigned u; asm("cvt.rna.tf32.f32 %0, %1;" : "=r"(u) : "f"(x)); return u;
}
__device__ __forceinline__ void mma_tf32(float c[4], const unsigned a[4],
                                         unsigned b0, unsigned b1) {
    asm volatile("mma.sync.aligned.m16n8k8.row.col.f32.tf32.tf32.f32 "
                 "{%0,%1,%2,%3},{%4,%5,%6,%7},{%8,%9},{%0,%1,%2,%3};"
                 : "+f"(c[0]), "+f"(c[1]), "+f"(c[2]), "+f"(c[3])
                 : "r"(a[0]), "r"(a[1]), "r"(a[2]), "r"(a[3]), "r"(b0), "r"(b1));
}
__device__ __forceinline__ float dot16(const float4 q[4], const float4* kr) {
    float4 k0 = kr[0], k1 = kr[1], k2 = kr[2], k3 = kr[3];
    float d = q[0].x*k0.x;
    d = fmaf(q[0].y, k0.y, d); d = fmaf(q[0].z, k0.z, d); d = fmaf(q[0].w, k0.w, d);
    d = fmaf(q[1].x, k1.x, d); d = fmaf(q[1].y, k1.y, d);
    d = fmaf(q[1].z, k1.z, d); d = fmaf(q[1].w, k1.w, d);
    d = fmaf(q[2].x, k2.x, d); d = fmaf(q[2].y, k2.y, d);
    d = fmaf(q[2].z, k2.z, d); d = fmaf(q[2].w, k2.w, d);
    d = fmaf(q[3].x, k3.x, d); d = fmaf(q[3].y, k3.y, d);
    d = fmaf(q[3].z, k3.z, d); d = fmaf(q[3].w, k3.w, d);
    return d;
}

// ---------------- rmsnorm ---------------------------------------------------
__global__ void rmsnorm_k(const float* __restrict__ x, const float* __restrict__ add,
                          const float* __restrict__ w, float* __restrict__ out) {
    int row  = blockIdx.x * 8 + (threadIdx.x >> 5);
    int lane = threadIdx.x & 31;
    float4 v = ((const float4*)(x + (size_t)row*Dv))[lane];
    if (add) {
        float4 a = ((const float4*)(add + (size_t)row*Dv))[lane];
        v.x += a.x; v.y += a.y; v.z += a.z; v.w += a.w;
    }
    float ss = v.x*v.x + v.y*v.y + v.z*v.z + v.w*v.w;
    #pragma unroll
    for (int off = 16; off; off >>= 1) ss += __shfl_xor_sync(0xffffffffu, ss, off);
    float s = rsqrtf(ss * (1.0f/Dv) + 1e-5f);
    float4 wv = ((const float4*)w)[lane];
    ((float4*)(out + (size_t)row*Dv))[lane] =
        make_float4(v.x*s*wv.x, v.y*s*wv.y, v.z*s*wv.z, v.w*s*wv.w);
}

// ---------------- tiled GEMM 64x64 ------------------------------------------
template<bool GELU, bool ADDC>
__global__ void gemm64(const float* __restrict__ A, const float* __restrict__ B,
                       const float* __restrict__ Cadd, float* __restrict__ C,
                       int M, int Nn, int K) {
    __shared__ float Ast[32*64];
    __shared__ float Bs [32*64];
    int tid = threadIdx.x;
    int bm = blockIdx.y, bn = blockIdx.x;
    int tx = tid & 15, ty = tid >> 4;
    float acc[4][4] = {};
    for (int k0 = 0; k0 < K; k0 += 32) {
        for (int u = tid; u < 512; u += 256) {
            int r = u >> 3, c4 = u & 7;
            float4 a = *(const float4*)&A[(size_t)(bm*64 + r)*K + k0 + c4*4];
            Ast[(c4*4+0)*64 + r] = a.x; Ast[(c4*4+1)*64 + r] = a.y;
            Ast[(c4*4+2)*64 + r] = a.z; Ast[(c4*4+3)*64 + r] = a.w;
        }
        for (int u = tid; u < 512; u += 256) {
            int kk = u >> 4, n4 = u & 15;
            *(float4*)&Bs[kk*64 + n4*4] =
                *(const float4*)&B[(size_t)(k0+kk)*Nn + bn*64 + n4*4];
        }
        __syncthreads();
        #pragma unroll
        for (int kk = 0; kk < 32; kk++) {
            float4 a4 = *(const float4*)&Ast[kk*64 + ty*4];
            float4 b4 = *(const float4*)&Bs [kk*64 + tx*4];
            float av[4] = {a4.x, a4.y, a4.z, a4.w};
            float bv[4] = {b4.x, b4.y, b4.z, b4.w};
            #pragma unroll
            for (int i = 0; i < 4; i++)
                #pragma unroll
                for (int j = 0; j < 4; j++)
                    acc[i][j] = fmaf(av[i], bv[j], acc[i][j]);
        }
        __syncthreads();
    }
    #pragma unroll
    for (int i = 0; i < 4; i++) {
        int r = bm*64 + ty*4 + i;
        #pragma unroll
        for (int j = 0; j < 4; j++) {
            int c = bn*64 + tx*4 + j;
            float v = acc[i][j];
            if (GELU) v = 0.5f * v * (1.0f + erff(v * 0.70710678118654752f));
            if (ADDC) v += Cadd[(size_t)r*Nn + c];
            C[(size_t)r*Nn + c] = v;
        }
    }
}

// ---------------- PASS 1: e12 = e @ W_e (tf32 mma, A direct from LDG) -------
__global__ void __launch_bounds__(256) eproj2_k(
    const float* __restrict__ e, const float* __restrict__ We,
    float* __restrict__ e12)
{
    __shared__ float2 sbhi[16*2*32];
    __shared__ float2 sblo[16*2*32];
    const int tid = threadIdx.x;
    const int warp = tid >> 5, lane = tid & 31;
    const int g = lane >> 2, t = lane & 3;

    if (warp == 0) {
        #pragma unroll
        for (int kk = 0; kk < 16; kk++) {
            int kkp = kk >> 1, s = kk & 1;
            int c0 = kkp*16 + 4*t + 2*s;
            #pragma unroll
            for (int nt = 0; nt < 2; nt++) {
                int n = nt*8 + g;
                int wcol = (n & 1)*Hv + (n >> 1);
                float w0 = We[c0*16 + wcol], w1 = We[(c0+1)*16 + wcol];
                unsigned h0 = cvt_tf32(w0), h1 = cvt_tf32(w1);
                sbhi[(kk*2+nt)*32 + lane] =
                    make_float2(__uint_as_float(h0), __uint_as_float(h1));
                sblo[(kk*2+nt)*32 + lane] = make_float2(
                    __uint_as_float(cvt_tf32(w0 - __uint_as_float(h0))),
                    __uint_as_float(cvt_tf32(w1 - __uint_as_float(h1))));
            }
        }
    }
    __syncthreads();

    for (int tile = blockIdx.x; tile < P1_NT; tile += gridDim.x) {
        const float4* A = (const float4*)(e + ((size_t)tile*128 + warp*16)*Dv);
        float c[2][4] = {};
        #pragma unroll
        for (int kkp = 0; kkp < 8; kkp++) {
            float4 alo = A[(size_t) g    *32 + kkp*4 + t];
            float4 ahi = A[(size_t)(g+8)*32 + kkp*4 + t];
            #pragma unroll
            for (int s = 0; s < 2; s++) {
                int kk = kkp*2 + s;
                float a0f = s ? alo.z : alo.x;
                float a1f = s ? ahi.z : ahi.x;
                float a2f = s ? alo.w : alo.y;
                float a3f = s ? ahi.w : ahi.y;
                unsigned ah[4] = {cvt_tf32(a0f), cvt_tf32(a1f),
                                  cvt_tf32(a2f), cvt_tf32(a3f)};
                unsigned al[4] = {
                    cvt_tf32(a0f - __uint_as_float(ah[0])),
                    cvt_tf32(a1f - __uint_as_float(ah[1])),
                    cvt_tf32(a2f - __uint_as_float(ah[2])),
                    cvt_tf32(a3f - __uint_as_float(ah[3]))};
                #pragma unroll
                for (int nt = 0; nt < 2; nt++) {
                    float2 bh = sbhi[(kk*2+nt)*32 + lane];
                    float2 bl = sblo[(kk*2+nt)*32 + lane];
                    unsigned b0 = __float_as_uint(bh.x), b1 = __float_as_uint(bh.y);
                    mma_tf32(c[nt], ah, b0, b1);
                    mma_tf32(c[nt], al, b0, b1);
                    mma_tf32(c[nt], ah, __float_as_uint(bl.x), __float_as_uint(bl.y));
                }
            }
        }
        float* out = e12 + ((size_t)tile*128 + warp*16)*16;
        #pragma unroll
        for (int nt = 0; nt < 2; nt++) {
            *(float2*)&out[ g    *16 + nt*8 + 2*t] = make_float2(c[nt][0], c[nt][1]);
            *(float2*)&out[(g+8)*16 + nt*8 + 2*t] = make_float2(c[nt][2], c[nt][3]);
        }
    }
}

// ---------------- PASS 2: attention, 2 i rows & full head frag per thread ---
// block = (b, 16 i), 512 thr; warp w: ip=w&7 (i-pair), jh=w>>3 (j half);
// lane: hh=lane>>2, jp=lane&3. Tiles hold 64 j (32 per half), double-buffered.
// k/v smem rows padded to KSTR=132 floats -> lane bank = 16*hh+4*jp (conflict-free).
#define ATTN_SMEM (2*2*64*KSTR*4)   // 132 KB

__global__ void __launch_bounds__(512, 1) attn4_k(
    const float* __restrict__ qkv, const float* __restrict__ e12,
    float* __restrict__ yout)
{
    extern __shared__ float sm[];
    float* ks = sm;                  // [2][64][KSTR]
    float* vs = sm + 2*64*KSTR;

    const int tid = threadIdx.x;
    const int b  = blockIdx.x >> 5;
    const int i0 = (blockIdx.x & 31) * 16;
    const int w = tid >> 5, lane = tid & 31;
    const int ip = w & 7, jh = w >> 3;
    const int hh = lane >> 2, jp = lane & 3;
    const int ia = i0 + ip*2, ib = ia + 1;

    float4 qa[4], qb[4];
    #pragma unroll
    for (int u = 0; u < 4; u++) {
        float4 q = *(const float4*)(qkv + (size_t)(b*Nv + ia)*384 + hh*16 + u*4);
        qa[u] = make_float4(q.x*0.25f, q.y*0.25f, q.z*0.25f, q.w*0.25f);
        q = *(const float4*)(qkv + (size_t)(b*Nv + ib)*384 + hh*16 + u*4);
        qb[u] = make_float4(q.x*0.25f, q.y*0.25f, q.z*0.25f, q.w*0.25f);
    }

    auto load_tile = [&](int t, int par) {
        #pragma unroll
        for (int ph = 0; ph < 4; ph++) {
            int u = tid + ph*512;          // 2048 slots: r 0..63, x4 0..31
            int r = u >> 5, x4 = u & 31;
            int jg = (r < 32) ? (t*32 + r) : (256 + t*32 + (r - 32));
            const float* src = qkv + (size_t)(b*Nv + jg)*384 + 128 + x4*4;
            cpa16(ks + par*64*KSTR + r*KSTR + x4*4, src);
            cpa16(vs + par*64*KSTR + r*KSTR + x4*4, src + 128);
        }
    };

    float4 aA[4] = {}, aB[4] = {};
    float dA = 0.f, dB = 0.f;

    load_tile(0, 0);
    cp_commit();
    for (int t = 0; t < 8; t++) {
        int par = t & 1;
        if (t + 1 < 8) load_tile(t + 1, par ^ 1);
        cp_commit();
        cp_wait1();
        __syncthreads();

        const float* kt = ks + par*64*KSTR + jh*32*KSTR;
        const float* vt = vs + par*64*KSTR + jh*32*KSTR;
        const float* eA = e12 + ((size_t)(b*Nv + ia)*Nv + jh*256 + t*32)*16 + hh*2;
        const float* eB = eA + (size_t)Nv*16;
        #pragma unroll
        for (int jj = 0; jj < 8; jj++) {
            int l = jj*4 + jp;
            const float4* kr = (const float4*)(kt + l*KSTR + hh*16);
            float da = dot16(qa, kr);
            float db = dot16(qb, kr);
            float2 eea = *(const float2*)(eA + l*16);
            float2 eeb = *(const float2*)(eB + l*16);
            float pa = __expf(da + eea.x);
            float pb = __expf(db + eeb.x);
            dA += pa; dB += pb;
            pa *= eea.y; pb *= eeb.y;
            const float4* vr = (const float4*)(vt + l*KSTR + hh*16);
            #pragma unroll
            for (int u = 0; u < 4; u++) {
                float4 vv = vr[u];
                aA[u].x = fmaf(pa, vv.x, aA[u].x);
                aA[u].y = fmaf(pa, vv.y, aA[u].y);
                aA[u].z = fmaf(pa, vv.z, aA[u].z);
                aA[u].w = fmaf(pa, vv.w, aA[u].w);
                aB[u].x = fmaf(pb, vv.x, aB[u].x);
                aB[u].y = fmaf(pb, vv.y, aB[u].y);
                aB[u].z = fmaf(pb, vv.z, aB[u].z);
                aB[u].w = fmaf(pb, vv.w, aB[u].w);
            }
        }
        __syncthreads();
    }

    // reduce over jp (lanes 0..3 within quad)
    #pragma unroll
    for (int s = 1; s <= 2; s <<= 1) {
        dA += __shfl_xor_sync(0xffffffffu, dA, s);
        dB += __shfl_xor_sync(0xffffffffu, dB, s);
        #pragma unroll
        for (int u = 0; u < 4; u++) {
            aA[u].x += __shfl_xor_sync(0xffffffffu, aA[u].x, s);
            aA[u].y += __shfl_xor_sync(0xffffffffu, aA[u].y, s);
            aA[u].z += __shfl_xor_sync(0xffffffffu, aA[u].z, s);
            aA[u].w += __shfl_xor_sync(0xffffffffu, aA[u].w, s);
            aB[u].x += __shfl_xor_sync(0xffffffffu, aB[u].x, s);
            aB[u].y += __shfl_xor_sync(0xffffffffu, aB[u].y, s);
            aB[u].z += __shfl_xor_sync(0xffffffffu, aB[u].z, s);
            aB[u].w += __shfl_xor_sync(0xffffffffu, aB[u].w, s);
        }
    }

    // exchange between j-halves via smem (reuse ks region).
    // float4 payload: row*8+hh at 16-float (64B-aligned) stride; dens separate.
    float* xb = sm;
    float* xd = sm + 16*8*16;
    __syncthreads();
    if (jh == 1) {
        float* pa = xb + ((ip*2 + 0)*8 + hh)*16;
        float* pb = xb + ((ip*2 + 1)*8 + hh)*16;
        *(float4*)(pa + jp*4) = aA[jp];
        *(float4*)(pb + jp*4) = aB[jp];
        if (jp == 0) {
            xd[(ip*2 + 0)*8 + hh] = dA;
            xd[(ip*2 + 1)*8 + hh] = dB;
        }
    }
    __syncthreads();
    if (jh == 0) {
        const float* pa = xb + ((ip*2 + 0)*8 + hh)*16;
        const float* pb = xb + ((ip*2 + 1)*8 + hh)*16;
        float4 oa = *(const float4*)(pa + jp*4);
        float4 ob = *(const float4*)(pb + jp*4);
        float invA = 1.0f / (dA + xd[(ip*2 + 0)*8 + hh]);
        float invB = 1.0f / (dB + xd[(ip*2 + 1)*8 + hh]);
        float4 ra = make_float4((aA[jp].x + oa.x)*invA, (aA[jp].y + oa.y)*invA,
                                (aA[jp].z + oa.z)*invA, (aA[jp].w + oa.w)*invA);
        float4 rb = make_float4((aB[jp].x + ob.x)*invB, (aB[jp].y + ob.y)*invB,
                                (aB[jp].z + ob.z)*invB, (aB[jp].w + ob.w)*invB);
        *(float4*)(yout + (size_t)(b*Nv + ia)*Dv + hh*16 + jp*4) = ra;
        *(float4*)(yout + (size_t)(b*Nv + ib)*Dv + hh*16 + jp*4) = rb;
    }
}

// ---------------- host launch ----------------------------------------------
extern "C" void kernel_launch(void* const* d_in, const int* in_sizes, int n_in,
                              void* d_out, int out_size) {
    const float* h    = (const float*)d_in[0];
    const float* e    = (const float*)d_in[1];
    const float* W_h  = (const float*)d_in[2];
    const float* W_e  = (const float*)d_in[3];
    const float* n1   = (const float*)d_in[4];
    const float* n2   = (const float*)d_in[5];
    const float* W_fc = (const float*)d_in[6];
    const float* W_pr = (const float*)d_in[7];
    float* out = (float*)d_out;

    float *p_hn, *p_qkv, *p_y, *p_z, *p_hid, *p_e12;
    cudaGetSymbolAddress((void**)&p_hn,  g_hn);
    cudaGetSymbolAddress((void**)&p_qkv, g_qkv);
    cudaGetSymbolAddress((void**)&p_y,   g_y);
    cudaGetSymbolAddress((void**)&p_z,   g_z);
    cudaGetSymbolAddress((void**)&p_hid, g_hid);
    cudaGetSymbolAddress((void**)&p_e12, g_e12);

    cudaFuncSetAttribute(attn4_k, cudaFuncAttributeMaxDynamicSharedMemorySize,
                         ATTN_SMEM);

    rmsnorm_k<<<ROWS/8, 256>>>(h, nullptr, n1, p_hn);
    gemm64<false,false><<<dim3(384/64, ROWS/64), 256>>>(p_hn, W_h, nullptr, p_qkv,
                                                        ROWS, 3*Dv, Dv);
    eproj2_k<<<592, 256>>>(e, W_e, p_e12);
    attn4_k<<<Bv*(Nv/16), 512, ATTN_SMEM>>>(p_qkv, p_e12, p_y);
    rmsnorm_k<<<ROWS/8, 256>>>(p_y, h, n2, p_z);
    gemm64<true,false><<<dim3(FFv/64, ROWS/64), 256>>>(p_z, W_fc, nullptr, p_hid,
                                                       ROWS, FFv, Dv);
    gemm64<false,true><<<dim3(Dv/64, ROWS/64), 256>>>(p_hid, W_pr, p_y, out,
                                                      ROWS, Dv, FFv);
}

// round 12
// speedup vs baseline: 1.7792x; 1.0073x over previous
#include <cuda_runtime.h>
#include <cstdint>

#define Bv   4
#define Nv   512
#define Dv   128
#define Hv   8
#define FFv  512
#define ROWS (Bv*Nv)
#define P1_NT 8192              // e tiles of 128 rows
#define KSTR 132                // padded k/v smem row stride (floats)

__device__ float g_hn [ROWS*Dv];
__device__ float g_qkv[ROWS*3*Dv];
__device__ float g_y  [ROWS*Dv];
__device__ float g_z  [ROWS*Dv];
__device__ float g_hid[ROWS*FFv];
__device__ float g_e12[(size_t)ROWS*Nv*16];   // 64 MB [b,i,j][h*2+{e1,e2}]

__device__ __forceinline__ void cpa16(void* s, const void* g) {
    unsigned sa = (unsigned)__cvta_generic_to_shared(s);
    asm volatile("cp.async.cg.shared.global [%0], [%1], 16;" :: "r"(sa), "l"(g));
}
__device__ __forceinline__ void cp_commit() { asm volatile("cp.async.commit_group;"); }
__device__ __forceinline__ void cp_wait1()  { asm volatile("cp.async.wait_group 1;" ::: "memory"); }

// packed bf16x2: (hi_elem -> upper 16, lo_elem -> lower 16)
__device__ __forceinline__ unsigned pack_bf(float hi, float lo) {
    unsigned r;
    asm("cvt.rn.bf16x2.f32 %0, %1, %2;" : "=r"(r) : "f"(hi), "f"(lo));
    return r;
}
// split (x0,x1) into bf16 hi pair + bf16 residual pair
__device__ __forceinline__ void bf_split(float x0, float x1,
                                         unsigned& hi, unsigned& lo) {
    hi = pack_bf(x1, x0);
    float h0 = __uint_as_float(hi << 16);
    float h1 = __uint_as_float(hi & 0xffff0000u);
    lo = pack_bf(x1 - h1, x0 - h0);
}
__device__ __forceinline__ void mma_bf16(float c[4], const unsigned a[4],
                                         unsigned b0, unsigned b1) {
    asm volatile("mma.sync.aligned.m16n8k16.row.col.f32.bf16.bf16.f32 "
                 "{%0,%1,%2,%3},{%4,%5,%6,%7},{%8,%9},{%0,%1,%2,%3};"
                 : "+f"(c[0]), "+f"(c[1]), "+f"(c[2]), "+f"(c[3])
                 : "r"(a[0]), "r"(a[1]), "r"(a[2]), "r"(a[3]), "r"(b0), "r"(b1));
}
__device__ __forceinline__ float dot16(const float4 q[4], const float4* kr) {
    float4 k0 = kr[0], k1 = kr[1], k2 = kr[2], k3 = kr[3];
    float d = q[0].x*k0.x;
    d = fmaf(q[0].y, k0.y, d); d = fmaf(q[0].z, k0.z, d); d = fmaf(q[0].w, k0.w, d);
    d = fmaf(q[1].x, k1.x, d); d = fmaf(q[1].y, k1.y, d);
    d = fmaf(q[1].z, k1.z, d); d = fmaf(q[1].w, k1.w, d);
    d = fmaf(q[2].x, k2.x, d); d = fmaf(q[2].y, k2.y, d);
    d = fmaf(q[2].z, k2.z, d); d = fmaf(q[2].w, k2.w, d);
    d = fmaf(q[3].x, k3.x, d); d = fmaf(q[3].y, k3.y, d);
    d = fmaf(q[3].z, k3.z, d); d = fmaf(q[3].w, k3.w, d);
    return d;
}

// ---------------- rmsnorm ---------------------------------------------------
__global__ void rmsnorm_k(const float* __restrict__ x, const float* __restrict__ add,
                          const float* __restrict__ w, float* __restrict__ out) {
    int row  = blockIdx.x * 8 + (threadIdx.x >> 5);
    int lane = threadIdx.x & 31;
    float4 v = ((const float4*)(x + (size_t)row*Dv))[lane];
    if (add) {
        float4 a = ((const float4*)(add + (size_t)row*Dv))[lane];
        v.x += a.x; v.y += a.y; v.z += a.z; v.w += a.w;
    }
    float ss = v.x*v.x + v.y*v.y + v.z*v.z + v.w*v.w;
    #pragma unroll
    for (int off = 16; off; off >>= 1) ss += __shfl_xor_sync(0xffffffffu, ss, off);
    float s = rsqrtf(ss * (1.0f/Dv) + 1e-5f);
    float4 wv = ((const float4*)w)[lane];
    ((float4*)(out + (size_t)row*Dv))[lane] =
        make_float4(v.x*s*wv.x, v.y*s*wv.y, v.z*s*wv.z, v.w*s*wv.w);
}

// ---------------- tiled GEMM 64x64 ------------------------------------------
template<bool GELU, bool ADDC>
__global__ void gemm64(const float* __restrict__ A, const float* __restrict__ B,
                       const float* __restrict__ Cadd, float* __restrict__ C,
                       int M, int Nn, int K) {
    __shared__ float Ast[32*64];
    __shared__ float Bs [32*64];
    int tid = threadIdx.x;
    int bm = blockIdx.y, bn = blockIdx.x;
    int tx = tid & 15, ty = tid >> 4;
    float acc[4][4] = {};
    for (int k0 = 0; k0 < K; k0 += 32) {
        for (int u = tid; u < 512; u += 256) {
            int r = u >> 3, c4 = u & 7;
            float4 a = *(const float4*)&A[(size_t)(bm*64 + r)*K + k0 + c4*4];
            Ast[(c4*4+0)*64 + r] = a.x; Ast[(c4*4+1)*64 + r] = a.y;
            Ast[(c4*4+2)*64 + r] = a.z; Ast[(c4*4+3)*64 + r] = a.w;
        }
        for (int u = tid; u < 512; u += 256) {
            int kk = u >> 4, n4 = u & 15;
            *(float4*)&Bs[kk*64 + n4*4] =
                *(const float4*)&B[(size_t)(k0+kk)*Nn + bn*64 + n4*4];
        }
        __syncthreads();
        #pragma unroll
        for (int kk = 0; kk < 32; kk++) {
            float4 a4 = *(const float4*)&Ast[kk*64 + ty*4];
            float4 b4 = *(const float4*)&Bs [kk*64 + tx*4];
            float av[4] = {a4.x, a4.y, a4.z, a4.w};
            float bv[4] = {b4.x, b4.y, b4.z, b4.w};
            #pragma unroll
            for (int i = 0; i < 4; i++)
                #pragma unroll
                for (int j = 0; j < 4; j++)
                    acc[i][j] = fmaf(av[i], bv[j], acc[i][j]);
        }
        __syncthreads();
    }
    #pragma unroll
    for (int i = 0; i < 4; i++) {
        int r = bm*64 + ty*4 + i;
        #pragma unroll
        for (int j = 0; j < 4; j++) {
            int c = bn*64 + tx*4 + j;
            float v = acc[i][j];
            if (GELU) v = 0.5f * v * (1.0f + erff(v * 0.70710678118654752f));
            if (ADDC) v += Cadd[(size_t)r*Nn + c];
            C[(size_t)r*Nn + c] = v;
        }
    }
}

// ---------------- PASS 1: e12 = e @ W_e (bf16 3-term split, m16n8k16) -------
// Per 16-k mma step kk: frag-k (2t,2t+1) -> cols kk*16+4t+{0,1};
// frag-k (2t+8,2t+9) -> cols kk*16+4t+{2,3}. Lane's A frag = own contig 16B.
__global__ void __launch_bounds__(256) eproj3_k(
    const float* __restrict__ e, const float* __restrict__ We,
    float* __restrict__ e12)
{
    __shared__ uint2 sbh[8*2*32];
    __shared__ uint2 sbl[8*2*32];
    const int tid = threadIdx.x;
    const int warp = tid >> 5, lane = tid & 31;
    const int g = lane >> 2, t = lane & 3;

    if (warp == 0) {
        #pragma unroll
        for (int kk = 0; kk < 8; kk++) {
            int c0 = kk*16 + 4*t;
            #pragma unroll
            for (int nt = 0; nt < 2; nt++) {
                int n = nt*8 + g;
                int wcol = (n & 1)*Hv + (n >> 1);
                float w0 = We[(c0+0)*16 + wcol];
                float w1 = We[(c0+1)*16 + wcol];
                float w2 = We[(c0+2)*16 + wcol];
                float w3 = We[(c0+3)*16 + wcol];
                unsigned h01, l01, h23, l23;
                bf_split(w0, w1, h01, l01);
                bf_split(w2, w3, h23, l23);
                sbh[(kk*2+nt)*32 + lane] = make_uint2(h01, h23);
                sbl[(kk*2+nt)*32 + lane] = make_uint2(l01, l23);
            }
        }
    }
    __syncthreads();

    for (int tile = blockIdx.x; tile < P1_NT; tile += gridDim.x) {
        const float4* A = (const float4*)(e + ((size_t)tile*128 + warp*16)*Dv);
        float c[2][4] = {};
        #pragma unroll
        for (int kk = 0; kk < 8; kk++) {
            float4 r0 = A[(size_t) g    *32 + kk*4 + t];
            float4 r1 = A[(size_t)(g+8)*32 + kk*4 + t];
            unsigned ah[4], al[4];
            bf_split(r0.x, r0.y, ah[0], al[0]);   // row g,   k-pair lo
            bf_split(r1.x, r1.y, ah[1], al[1]);   // row g+8, k-pair lo
            bf_split(r0.z, r0.w, ah[2], al[2]);   // row g,   k-pair hi
            bf_split(r1.z, r1.w, ah[3], al[3]);   // row g+8, k-pair hi
            #pragma unroll
            for (int nt = 0; nt < 2; nt++) {
                uint2 bh = sbh[(kk*2+nt)*32 + lane];
                uint2 bl = sbl[(kk*2+nt)*32 + lane];
                mma_bf16(c[nt], ah, bh.x, bh.y);   // hi*hi
                mma_bf16(c[nt], al, bh.x, bh.y);   // lo*hi
                mma_bf16(c[nt], ah, bl.x, bl.y);   // hi*lo
            }
        }
        float* out = e12 + ((size_t)tile*128 + warp*16)*16;
        #pragma unroll
        for (int nt = 0; nt < 2; nt++) {
            *(float2*)&out[ g    *16 + nt*8 + 2*t] = make_float2(c[nt][0], c[nt][1]);
            *(float2*)&out[(g+8)*16 + nt*8 + 2*t] = make_float2(c[nt][2], c[nt][3]);
        }
    }
}

// ---------------- PASS 2: attention (2 i rows + full head frag per thread) --
#define ATTN_SMEM (2*2*64*KSTR*4)   // 132 KB

__global__ void __launch_bounds__(512, 1) attn4_k(
    const float* __restrict__ qkv, const float* __restrict__ e12,
    float* __restrict__ yout)
{
    extern __shared__ float sm[];
    float* ks = sm;                  // [2][64][KSTR]
    float* vs = sm + 2*64*KSTR;

    const int tid = threadIdx.x;
    const int b  = blockIdx.x >> 5;
    const int i0 = (blockIdx.x & 31) * 16;
    const int w = tid >> 5, lane = tid & 31;
    const int ip = w & 7, jh = w >> 3;
    const int hh = lane >> 2, jp = lane & 3;
    const int ia = i0 + ip*2, ib = ia + 1;

    float4 qa[4], qb[4];
    #pragma unroll
    for (int u = 0; u < 4; u++) {
        float4 q = *(const float4*)(qkv + (size_t)(b*Nv + ia)*384 + hh*16 + u*4);
        qa[u] = make_float4(q.x*0.25f, q.y*0.25f, q.z*0.25f, q.w*0.25f);
        q = *(const float4*)(qkv + (size_t)(b*Nv + ib)*384 + hh*16 + u*4);
        qb[u] = make_float4(q.x*0.25f, q.y*0.25f, q.z*0.25f, q.w*0.25f);
    }

    auto load_tile = [&](int t, int par) {
        #pragma unroll
        for (int ph = 0; ph < 4; ph++) {
            int u = tid + ph*512;
            int r = u >> 5, x4 = u & 31;
            int jg = (r < 32) ? (t*32 + r) : (256 + t*32 + (r - 32));
            const float* src = qkv + (size_t)(b*Nv + jg)*384 + 128 + x4*4;
            cpa16(ks + par*64*KSTR + r*KSTR + x4*4, src);
            cpa16(vs + par*64*KSTR + r*KSTR + x4*4, src + 128);
        }
    };

    float4 aA[4] = {}, aB[4] = {};
    float dA = 0.f, dB = 0.f;

    load_tile(0, 0);
    cp_commit();
    for (int t = 0; t < 8; t++) {
        int par = t & 1;
        if (t + 1 < 8) load_tile(t + 1, par ^ 1);
        cp_commit();
        cp_wait1();
        __syncthreads();

        const float* kt = ks + par*64*KSTR + jh*32*KSTR;
        const float* vt = vs + par*64*KSTR + jh*32*KSTR;
        const float* eA = e12 + ((size_t)(b*Nv + ia)*Nv + jh*256 + t*32)*16 + hh*2;
        const float* eB = eA + (size_t)Nv*16;
        #pragma unroll
        for (int jj = 0; jj < 8; jj++) {
            int l = jj*4 + jp;
            const float4* kr = (const float4*)(kt + l*KSTR + hh*16);
            float da = dot16(qa, kr);
            float db = dot16(qb, kr);
            float2 eea = *(const float2*)(eA + l*16);
            float2 eeb = *(const float2*)(eB + l*16);
            float pa = __expf(da + eea.x);
            float pb = __expf(db + eeb.x);
            dA += pa; dB += pb;
            pa *= eea.y; pb *= eeb.y;
            const float4* vr = (const float4*)(vt + l*KSTR + hh*16);
            #pragma unroll
            for (int u = 0; u < 4; u++) {
                float4 vv = vr[u];
                aA[u].x = fmaf(pa, vv.x, aA[u].x);
                aA[u].y = fmaf(pa, vv.y, aA[u].y);
                aA[u].z = fmaf(pa, vv.z, aA[u].z);
                aA[u].w = fmaf(pa, vv.w, aA[u].w);
                aB[u].x = fmaf(pb, vv.x, aB[u].x);
                aB[u].y = fmaf(pb, vv.y, aB[u].y);
                aB[u].z = fmaf(pb, vv.z, aB[u].z);
                aB[u].w = fmaf(pb, vv.w, aB[u].w);
            }
        }
        __syncthreads();
    }

    #pragma unroll
    for (int s = 1; s <= 2; s <<= 1) {
        dA += __shfl_xor_sync(0xffffffffu, dA, s);
        dB += __shfl_xor_sync(0xffffffffu, dB, s);
        #pragma unroll
        for (int u = 0; u < 4; u++) {
            aA[u].x += __shfl_xor_sync(0xffffffffu, aA[u].x, s);
            aA[u].y += __shfl_xor_sync(0xffffffffu, aA[u].y, s);
            aA[u].z += __shfl_xor_sync(0xffffffffu, aA[u].z, s);
            aA[u].w += __shfl_xor_sync(0xffffffffu, aA[u].w, s);
            aB[u].x += __shfl_xor_sync(0xffffffffu, aB[u].x, s);
            aB[u].y += __shfl_xor_sync(0xffffffffu, aB[u].y, s);
            aB[u].z += __shfl_xor_sync(0xffffffffu, aB[u].z, s);
            aB[u].w += __shfl_xor_sync(0xffffffffu, aB[u].w, s);
        }
    }

    float* xb = sm;
    float* xd = sm + 16*8*16;
    __syncthreads();
    if (jh == 1) {
        float* pa = xb + ((ip*2 + 0)*8 + hh)*16;
        float* pb = xb + ((ip*2 + 1)*8 + hh)*16;
        *(float4*)(pa + jp*4) = aA[jp];
        *(float4*)(pb + jp*4) = aB[jp];
        if (jp == 0) {
            xd[(ip*2 + 0)*8 + hh] = dA;
            xd[(ip*2 + 1)*8 + hh] = dB;
        }
    }
    __syncthreads();
    if (jh == 0) {
        const float* pa = xb + ((ip*2 + 0)*8 + hh)*16;
        const float* pb = xb + ((ip*2 + 1)*8 + hh)*16;
        float4 oa = *(const float4*)(pa + jp*4);
        float4 ob = *(const float4*)(pb + jp*4);
        float invA = 1.0f / (dA + xd[(ip*2 + 0)*8 + hh]);
        float invB = 1.0f / (dB + xd[(ip*2 + 1)*8 + hh]);
        float4 ra = make_float4((aA[jp].x + oa.x)*invA, (aA[jp].y + oa.y)*invA,
                                (aA[jp].z + oa.z)*invA, (aA[jp].w + oa.w)*invA);
        float4 rb = make_float4((aB[jp].x + ob.x)*invB, (aB[jp].y + ob.y)*invB,
                                (aB[jp].z + ob.z)*invB, (aB[jp].w + ob.w)*invB);
        *(float4*)(yout + (size_t)(b*Nv + ia)*Dv + hh*16 + jp*4) = ra;
        *(float4*)(yout + (size_t)(b*Nv + ib)*Dv + hh*16 + jp*4) = rb;
    }
}

// ---------------- host launch ----------------------------------------------
extern "C" void kernel_launch(void* const* d_in, const int* in_sizes, int n_in,
                              void* d_out, int out_size) {
    const float* h    = (const float*)d_in[0];
    const float* e    = (const float*)d_in[1];
    const float* W_h  = (const float*)d_in[2];
    const float* W_e  = (const float*)d_in[3];
    const float* n1   = (const float*)d_in[4];
    const float* n2   = (const float*)d_in[5];
    const float* W_fc = (const float*)d_in[6];
    const float* W_pr = (const float*)d_in[7];
    float* out = (float*)d_out;

    float *p_hn, *p_qkv, *p_y, *p_z, *p_hid, *p_e12;
    cudaGetSymbolAddress((void**)&p_hn,  g_hn);
    cudaGetSymbolAddress((void**)&p_qkv, g_qkv);
    cudaGetSymbolAddress((void**)&p_y,   g_y);
    cudaGetSymbolAddress((void**)&p_z,   g_z);
    cudaGetSymbolAddress((void**)&p_hid, g_hid);
    cudaGetSymbolAddress((void**)&p_e12, g_e12);

    cudaFuncSetAttribute(attn4_k, cudaFuncAttributeMaxDynamicSharedMemorySize,
                         ATTN_SMEM);

    rmsnorm_k<<<ROWS/8, 256>>>(h, nullptr, n1, p_hn);
    gemm64<false,false><<<dim3(384/64, ROWS/64), 256>>>(p_hn, W_h, nullptr, p_qkv,
                                                        ROWS, 3*Dv, Dv);
    eproj3_k<<<592, 256>>>(e, W_e, p_e12);
    attn4_k<<<Bv*(Nv/16), 512, ATTN_SMEM>>>(p_qkv, p_e12, p_y);
    rmsnorm_k<<<ROWS/8, 256>>>(p_y, h, n2, p_z);
    gemm64<true,false><<<dim3(FFv/64, ROWS/64), 256>>>(p_z, W_fc, nullptr, p_hid,
                                                       ROWS, FFv, Dv);
    gemm64<false,true><<<dim3(Dv/64, ROWS/64), 256>>>(p_hid, W_pr, p_y, out,
                                                      ROWS, Dv, FFv);
}

// round 13
// speedup vs baseline: 1.8298x; 1.0284x over previous
#include <cuda_runtime.h>
#include <cstdint>

#define Bv   4
#define Nv   512
#define Dv   128
#define Hv   8
#define FFv  512
#define ROWS (Bv*Nv)
#define P1_NT 8192              // e tiles of 128 rows
#define KSTR 132                // padded k/v smem row stride (floats, attn)
#define ESTR 144                // padded e smem row stride (floats, eproj) ≡16 mod 32
#define EPROJ_GRID 148

__device__ float g_hn [ROWS*Dv];
__device__ float g_qkv[ROWS*3*Dv];
__device__ float g_y  [ROWS*Dv];
__device__ float g_z  [ROWS*Dv];
__device__ float g_hid[ROWS*FFv];
__device__ float g_e12[(size_t)ROWS*Nv*16];   // 64 MB [b,i,j][h*2+{e1,e2}]

__device__ __forceinline__ void cpa16(void* s, const void* g) {
    unsigned sa = (unsigned)__cvta_generic_to_shared(s);
    asm volatile("cp.async.cg.shared.global [%0], [%1], 16;" :: "r"(sa), "l"(g));
}
__device__ __forceinline__ void cp_commit() { asm volatile("cp.async.commit_group;"); }
__device__ __forceinline__ void cp_wait1()  { asm volatile("cp.async.wait_group 1;" ::: "memory"); }

// packed bf16x2 helpers
__device__ __forceinline__ unsigned pack_bf(float hi, float lo) {
    unsigned r;
    asm("cvt.rn.bf16x2.f32 %0, %1, %2;" : "=r"(r) : "f"(hi), "f"(lo));
    return r;
}
__device__ __forceinline__ void bf_split(float x0, float x1,
                                         unsigned& hi, unsigned& lo) {
    hi = pack_bf(x1, x0);
    float h0 = __uint_as_float(hi << 16);
    float h1 = __uint_as_float(hi & 0xffff0000u);
    lo = pack_bf(x1 - h1, x0 - h0);
}
__device__ __forceinline__ void mma_bf16(float c[4], const unsigned a[4],
                                         unsigned b0, unsigned b1) {
    asm volatile("mma.sync.aligned.m16n8k16.row.col.f32.bf16.bf16.f32 "
                 "{%0,%1,%2,%3},{%4,%5,%6,%7},{%8,%9},{%0,%1,%2,%3};"
                 : "+f"(c[0]), "+f"(c[1]), "+f"(c[2]), "+f"(c[3])
                 : "r"(a[0]), "r"(a[1]), "r"(a[2]), "r"(a[3]), "r"(b0), "r"(b1));
}
__device__ __forceinline__ float dot16(const float4 q[4], const float4* kr) {
    float4 k0 = kr[0], k1 = kr[1], k2 = kr[2], k3 = kr[3];
    float d = q[0].x*k0.x;
    d = fmaf(q[0].y, k0.y, d); d = fmaf(q[0].z, k0.z, d); d = fmaf(q[0].w, k0.w, d);
    d = fmaf(q[1].x, k1.x, d); d = fmaf(q[1].y, k1.y, d);
    d = fmaf(q[1].z, k1.z, d); d = fmaf(q[1].w, k1.w, d);
    d = fmaf(q[2].x, k2.x, d); d = fmaf(q[2].y, k2.y, d);
    d = fmaf(q[2].z, k2.z, d); d = fmaf(q[2].w, k2.w, d);
    d = fmaf(q[3].x, k3.x, d); d = fmaf(q[3].y, k3.y, d);
    d = fmaf(q[3].z, k3.z, d); d = fmaf(q[3].w, k3.w, d);
    return d;
}

__global__ void noop_k() {}

// ---------------- rmsnorm ---------------------------------------------------
__global__ void rmsnorm_k(const float* __restrict__ x, const float* __restrict__ add,
                          const float* __restrict__ w, float* __restrict__ out) {
    int row  = blockIdx.x * 8 + (threadIdx.x >> 5);
    int lane = threadIdx.x & 31;
    float4 v = ((const float4*)(x + (size_t)row*Dv))[lane];
    if (add) {
        float4 a = ((const float4*)(add + (size_t)row*Dv))[lane];
        v.x += a.x; v.y += a.y; v.z += a.z; v.w += a.w;
    }
    float ss = v.x*v.x + v.y*v.y + v.z*v.z + v.w*v.w;
    #pragma unroll
    for (int off = 16; off; off >>= 1) ss += __shfl_xor_sync(0xffffffffu, ss, off);
    float s = rsqrtf(ss * (1.0f/Dv) + 1e-5f);
    float4 wv = ((const float4*)w)[lane];
    ((float4*)(out + (size_t)row*Dv))[lane] =
        make_float4(v.x*s*wv.x, v.y*s*wv.y, v.z*s*wv.z, v.w*s*wv.w);
}

// ---------------- tiled GEMM 64x64 ------------------------------------------
template<bool GELU, bool ADDC>
__global__ void gemm64(const float* __restrict__ A, const float* __restrict__ B,
                       const float* __restrict__ Cadd, float* __restrict__ C,
                       int M, int Nn, int K) {
    __shared__ float Ast[32*64];
    __shared__ float Bs [32*64];
    int tid = threadIdx.x;
    int bm = blockIdx.y, bn = blockIdx.x;
    int tx = tid & 15, ty = tid >> 4;
    float acc[4][4] = {};
    for (int k0 = 0; k0 < K; k0 += 32) {
        for (int u = tid; u < 512; u += 256) {
            int r = u >> 3, c4 = u & 7;
            float4 a = *(const float4*)&A[(size_t)(bm*64 + r)*K + k0 + c4*4];
            Ast[(c4*4+0)*64 + r] = a.x; Ast[(c4*4+1)*64 + r] = a.y;
            Ast[(c4*4+2)*64 + r] = a.z; Ast[(c4*4+3)*64 + r] = a.w;
        }
        for (int u = tid; u < 512; u += 256) {
            int kk = u >> 4, n4 = u & 15;
            *(float4*)&Bs[kk*64 + n4*4] =
                *(const float4*)&B[(size_t)(k0+kk)*Nn + bn*64 + n4*4];
        }
        __syncthreads();
        #pragma unroll
        for (int kk = 0; kk < 32; kk++) {
            float4 a4 = *(const float4*)&Ast[kk*64 + ty*4];
            float4 b4 = *(const float4*)&Bs [kk*64 + tx*4];
            float av[4] = {a4.x, a4.y, a4.z, a4.w};
            float bv[4] = {b4.x, b4.y, b4.z, b4.w};
            #pragma unroll
            for (int i = 0; i < 4; i++)
                #pragma unroll
                for (int j = 0; j < 4; j++)
                    acc[i][j] = fmaf(av[i], bv[j], acc[i][j]);
        }
        __syncthreads();
    }
    #pragma unroll
    for (int i = 0; i < 4; i++) {
        int r = bm*64 + ty*4 + i;
        #pragma unroll
        for (int j = 0; j < 4; j++) {
            int c = bn*64 + tx*4 + j;
            float v = acc[i][j];
            if (GELU) v = 0.5f * v * (1.0f + erff(v * 0.70710678118654752f));
            if (ADDC) v += Cadd[(size_t)r*Nn + c];
            C[(size_t)r*Nn + c] = v;
        }
    }
}

// ---------------- PASS 1: e12 = e @ W_e (cp.async staged, bf16 3-term) ------
// smem stages: [2][128 rows][ESTR floats]; compute LDS lane bank =
// (16g + 16kk + 4t) mod 32 -> conflict-free.
#define EP_SMEM (2*128*ESTR*4)

__global__ void __launch_bounds__(256, 1) eproj4_k(
    const float* __restrict__ e, const float* __restrict__ We,
    float* __restrict__ e12)
{
    extern __shared__ float sa[];                  // [2][128][ESTR]
    __shared__ uint2 sbh[8*2*32];
    __shared__ uint2 sbl[8*2*32];

    const int tid = threadIdx.x;
    const int warp = tid >> 5, lane = tid & 31;
    const int g = lane >> 2, t = lane & 3;

    if (warp == 0) {
        #pragma unroll
        for (int kk = 0; kk < 8; kk++) {
            int c0 = kk*16 + 4*t;
            #pragma unroll
            for (int nt = 0; nt < 2; nt++) {
                int n = nt*8 + g;
                int wcol = (n & 1)*Hv + (n >> 1);
                float w0 = We[(c0+0)*16 + wcol];
                float w1 = We[(c0+1)*16 + wcol];
                float w2 = We[(c0+2)*16 + wcol];
                float w3 = We[(c0+3)*16 + wcol];
                unsigned h01, l01, h23, l23;
                bf_split(w0, w1, h01, l01);
                bf_split(w2, w3, h23, l23);
                sbh[(kk*2+nt)*32 + lane] = make_uint2(h01, h23);
                sbl[(kk*2+nt)*32 + lane] = make_uint2(l01, l23);
            }
        }
    }
    __syncthreads();

    auto load_tile = [&](int tile, int par) {
        const float* src = e + (size_t)tile*128*Dv;
        float* dst = sa + par*128*ESTR;
        #pragma unroll
        for (int ph = 0; ph < 16; ph++) {
            int u = tid + ph*256;                 // 4096 chunks: r=u>>5, x4=u&31
            int r = u >> 5, x4 = u & 31;
            cpa16(dst + r*ESTR + x4*4, src + (size_t)r*Dv + x4*4);
        }
    };

    int tile = blockIdx.x;
    load_tile(tile, 0);
    cp_commit();
    int par = 0;
    for (; tile < P1_NT; tile += gridDim.x) {
        int nxt = tile + gridDim.x;
        if (nxt < P1_NT) load_tile(nxt, par ^ 1);
        cp_commit();
        cp_wait1();
        __syncthreads();

        const float* A = sa + par*128*ESTR + warp*16*ESTR;
        float c[2][4] = {};
        #pragma unroll
        for (int kk = 0; kk < 8; kk++) {
            float4 r0 = *(const float4*)(A + (size_t) g    *ESTR + kk*16 + t*4);
            float4 r1 = *(const float4*)(A + (size_t)(g+8)*ESTR + kk*16 + t*4);
            unsigned ah[4], al[4];
            bf_split(r0.x, r0.y, ah[0], al[0]);
            bf_split(r1.x, r1.y, ah[1], al[1]);
            bf_split(r0.z, r0.w, ah[2], al[2]);
            bf_split(r1.z, r1.w, ah[3], al[3]);
            #pragma unroll
            for (int nt = 0; nt < 2; nt++) {
                uint2 bh = sbh[(kk*2+nt)*32 + lane];
                uint2 bl = sbl[(kk*2+nt)*32 + lane];
                mma_bf16(c[nt], ah, bh.x, bh.y);
                mma_bf16(c[nt], al, bh.x, bh.y);
                mma_bf16(c[nt], ah, bl.x, bl.y);
            }
        }
        float* out = e12 + ((size_t)tile*128 + warp*16)*16;
        #pragma unroll
        for (int nt = 0; nt < 2; nt++) {
            *(float2*)&out[ g    *16 + nt*8 + 2*t] = make_float2(c[nt][0], c[nt][1]);
            *(float2*)&out[(g+8)*16 + nt*8 + 2*t] = make_float2(c[nt][2], c[nt][3]);
        }
        __syncthreads();
        par ^= 1;
    }
}

// ---------------- PASS 2: attention (2 i rows + full head frag per thread) --
#define ATTN_SMEM (2*2*64*KSTR*4)   // 132 KB

__global__ void __launch_bounds__(512, 1) attn4_k(
    const float* __restrict__ qkv, const float* __restrict__ e12,
    float* __restrict__ yout)
{
    extern __shared__ float sm[];
    float* ks = sm;                  // [2][64][KSTR]
    float* vs = sm + 2*64*KSTR;

    const int tid = threadIdx.x;
    const int b  = blockIdx.x >> 5;
    const int i0 = (blockIdx.x & 31) * 16;
    const int w = tid >> 5, lane = tid & 31;
    const int ip = w & 7, jh = w >> 3;
    const int hh = lane >> 2, jp = lane & 3;
    const int ia = i0 + ip*2, ib = ia + 1;

    float4 qa[4], qb[4];
    #pragma unroll
    for (int u = 0; u < 4; u++) {
        float4 q = *(const float4*)(qkv + (size_t)(b*Nv + ia)*384 + hh*16 + u*4);
        qa[u] = make_float4(q.x*0.25f, q.y*0.25f, q.z*0.25f, q.w*0.25f);
        q = *(const float4*)(qkv + (size_t)(b*Nv + ib)*384 + hh*16 + u*4);
        qb[u] = make_float4(q.x*0.25f, q.y*0.25f, q.z*0.25f, q.w*0.25f);
    }

    auto load_tile = [&](int t, int par) {
        #pragma unroll
        for (int ph = 0; ph < 4; ph++) {
            int u = tid + ph*512;
            int r = u >> 5, x4 = u & 31;
            int jg = (r < 32) ? (t*32 + r) : (256 + t*32 + (r - 32));
            const float* src = qkv + (size_t)(b*Nv + jg)*384 + 128 + x4*4;
            cpa16(ks + par*64*KSTR + r*KSTR + x4*4, src);
            cpa16(vs + par*64*KSTR + r*KSTR + x4*4, src + 128);
        }
    };

    float4 aA[4] = {}, aB[4] = {};
    float dA = 0.f, dB = 0.f;

    load_tile(0, 0);
    cp_commit();
    for (int t = 0; t < 8; t++) {
        int par = t & 1;
        if (t + 1 < 8) load_tile(t + 1, par ^ 1);
        cp_commit();
        cp_wait1();
        __syncthreads();

        const float* kt = ks + par*64*KSTR + jh*32*KSTR;
        const float* vt = vs + par*64*KSTR + jh*32*KSTR;
        const float* eA = e12 + ((size_t)(b*Nv + ia)*Nv + jh*256 + t*32)*16 + hh*2;
        const float* eB = eA + (size_t)Nv*16;
        #pragma unroll
        for (int jj = 0; jj < 8; jj++) {
            int l = jj*4 + jp;
            const float4* kr = (const float4*)(kt + l*KSTR + hh*16);
            float da = dot16(qa, kr);
            float db = dot16(qb, kr);
            float2 eea = *(const float2*)(eA + l*16);
            float2 eeb = *(const float2*)(eB + l*16);
            float pa = __expf(da + eea.x);
            float pb = __expf(db + eeb.x);
            dA += pa; dB += pb;
            pa *= eea.y; pb *= eeb.y;
            const float4* vr = (const float4*)(vt + l*KSTR + hh*16);
            #pragma unroll
            for (int u = 0; u < 4; u++) {
                float4 vv = vr[u];
                aA[u].x = fmaf(pa, vv.x, aA[u].x);
                aA[u].y = fmaf(pa, vv.y, aA[u].y);
                aA[u].z = fmaf(pa, vv.z, aA[u].z);
                aA[u].w = fmaf(pa, vv.w, aA[u].w);
                aB[u].x = fmaf(pb, vv.x, aB[u].x);
                aB[u].y = fmaf(pb, vv.y, aB[u].y);
                aB[u].z = fmaf(pb, vv.z, aB[u].z);
                aB[u].w = fmaf(pb, vv.w, aB[u].w);
            }
        }
        __syncthreads();
    }

    #pragma unroll
    for (int s = 1; s <= 2; s <<= 1) {
        dA += __shfl_xor_sync(0xffffffffu, dA, s);
        dB += __shfl_xor_sync(0xffffffffu, dB, s);
        #pragma unroll
        for (int u = 0; u < 4; u++) {
            aA[u].x += __shfl_xor_sync(0xffffffffu, aA[u].x, s);
            aA[u].y += __shfl_xor_sync(0xffffffffu, aA[u].y, s);
            aA[u].z += __shfl_xor_sync(0xffffffffu, aA[u].z, s);
            aA[u].w += __shfl_xor_sync(0xffffffffu, aA[u].w, s);
            aB[u].x += __shfl_xor_sync(0xffffffffu, aB[u].x, s);
            aB[u].y += __shfl_xor_sync(0xffffffffu, aB[u].y, s);
            aB[u].z += __shfl_xor_sync(0xffffffffu, aB[u].z, s);
            aB[u].w += __shfl_xor_sync(0xffffffffu, aB[u].w, s);
        }
    }

    float* xb = sm;
    float* xd = sm + 16*8*16;
    __syncthreads();
    if (jh == 1) {
        float* pa = xb + ((ip*2 + 0)*8 + hh)*16;
        float* pb = xb + ((ip*2 + 1)*8 + hh)*16;
        *(float4*)(pa + jp*4) = aA[jp];
        *(float4*)(pb + jp*4) = aB[jp];
        if (jp == 0) {
            xd[(ip*2 + 0)*8 + hh] = dA;
            xd[(ip*2 + 1)*8 + hh] = dB;
        }
    }
    __syncthreads();
    if (jh == 0) {
        const float* pa = xb + ((ip*2 + 0)*8 + hh)*16;
        const float* pb = xb + ((ip*2 + 1)*8 + hh)*16;
        float4 oa = *(const float4*)(pa + jp*4);
        float4 ob = *(const float4*)(pb + jp*4);
        float invA = 1.0f / (dA + xd[(ip*2 + 0)*8 + hh]);
        float invB = 1.0f / (dB + xd[(ip*2 + 1)*8 + hh]);
        float4 ra = make_float4((aA[jp].x + oa.x)*invA, (aA[jp].y + oa.y)*invA,
                                (aA[jp].z + oa.z)*invA, (aA[jp].w + oa.w)*invA);
        float4 rb = make_float4((aB[jp].x + ob.x)*invB, (aB[jp].y + ob.y)*invB,
                                (aB[jp].z + ob.z)*invB, (aB[jp].w + ob.w)*invB);
        *(float4*)(yout + (size_t)(b*Nv + ia)*Dv + hh*16 + jp*4) = ra;
        *(float4*)(yout + (size_t)(b*Nv + ib)*Dv + hh*16 + jp*4) = rb;
    }
}

// ---------------- host launch ----------------------------------------------
extern "C" void kernel_launch(void* const* d_in, const int* in_sizes, int n_in,
                              void* d_out, int out_size) {
    const float* h    = (const float*)d_in[0];
    const float* e    = (const float*)d_in[1];
    const float* W_h  = (const float*)d_in[2];
    const float* W_e  = (const float*)d_in[3];
    const float* n1   = (const float*)d_in[4];
    const float* n2   = (const float*)d_in[5];
    const float* W_fc = (const float*)d_in[6];
    const float* W_pr = (const float*)d_in[7];
    float* out = (float*)d_out;

    float *p_hn, *p_qkv, *p_y, *p_z, *p_hid, *p_e12;
    cudaGetSymbolAddress((void**)&p_hn,  g_hn);
    cudaGetSymbolAddress((void**)&p_qkv, g_qkv);
    cudaGetSymbolAddress((void**)&p_y,   g_y);
    cudaGetSymbolAddress((void**)&p_z,   g_z);
    cudaGetSymbolAddress((void**)&p_hid, g_hid);
    cudaGetSymbolAddress((void**)&p_e12, g_e12);

    cudaFuncSetAttribute(attn4_k, cudaFuncAttributeMaxDynamicSharedMemorySize,
                         ATTN_SMEM);
    cudaFuncSetAttribute(eproj4_k, cudaFuncAttributeMaxDynamicSharedMemorySize,
                         EP_SMEM);

    rmsnorm_k<<<ROWS/8, 256>>>(h, nullptr, n1, p_hn);                 // launch 1
    gemm64<false,false><<<dim3(384/64, ROWS/64), 256>>>(p_hn, W_h, nullptr,
                                                        p_qkv, ROWS, 3*Dv, Dv); // 2
    noop_k<<<1, 32>>>();                                              // 3 (shifts
    eproj4_k<<<EPROJ_GRID, 256, EP_SMEM>>>(e, W_e, p_e12);            // 4 <- ncu)
    attn4_k<<<Bv*(Nv/16), 512, ATTN_SMEM>>>(p_qkv, p_e12, p_y);       // 5
    rmsnorm_k<<<ROWS/8, 256>>>(p_y, h, n2, p_z);                      // 6
    gemm64<true,false><<<dim3(FFv/64, ROWS/64), 256>>>(p_z, W_fc, nullptr,
                                                       p_hid, ROWS, FFv, Dv);   // 7
    gemm64<false,true><<<dim3(Dv/64, ROWS/64), 256>>>(p_hid, W_pr, p_y, out,
                                                      ROWS, Dv, FFv);           // 8
}

// round 14
// speedup vs baseline: 1.9635x; 1.0731x over previous
#include <cuda_runtime.h>
#include <cuda_fp16.h>
#include <cstdint>

#define Bv   4
#define Nv   512
#define Dv   128
#define Hv   8
#define FFv  512
#define ROWS (Bv*Nv)
#define P1_NT 8192              // e tiles of 128 rows
#define KSTR 132                // padded k/v smem row stride (floats, attn)
#define ESTR 144                // padded e smem row stride (floats, eproj)
#define EPROJ_GRID 148

__device__ float   g_qkv[ROWS*3*Dv];
__device__ float   g_y  [ROWS*Dv];
__device__ float   g_hid[ROWS*FFv];
__device__ __half2 g_e12[(size_t)ROWS*Nv*8];   // 32 MB [b,i,j][h] = (e1,e2)

__device__ __forceinline__ void cpa16(void* s, const void* g) {
    unsigned sa = (unsigned)__cvta_generic_to_shared(s);
    asm volatile("cp.async.cg.shared.global [%0], [%1], 16;" :: "r"(sa), "l"(g));
}
__device__ __forceinline__ void cp_commit() { asm volatile("cp.async.commit_group;"); }
__device__ __forceinline__ void cp_wait1()  { asm volatile("cp.async.wait_group 1;" ::: "memory"); }

__device__ __forceinline__ unsigned pack_bf(float hi, float lo) {
    unsigned r;
    asm("cvt.rn.bf16x2.f32 %0, %1, %2;" : "=r"(r) : "f"(hi), "f"(lo));
    return r;
}
__device__ __forceinline__ void bf_split(float x0, float x1,
                                         unsigned& hi, unsigned& lo) {
    hi = pack_bf(x1, x0);
    float h0 = __uint_as_float(hi << 16);
    float h1 = __uint_as_float(hi & 0xffff0000u);
    lo = pack_bf(x1 - h1, x0 - h0);
}
__device__ __forceinline__ void mma_bf16(float c[4], const unsigned a[4],
                                         unsigned b0, unsigned b1) {
    asm volatile("mma.sync.aligned.m16n8k16.row.col.f32.bf16.bf16.f32 "
                 "{%0,%1,%2,%3},{%4,%5,%6,%7},{%8,%9},{%0,%1,%2,%3};"
                 : "+f"(c[0]), "+f"(c[1]), "+f"(c[2]), "+f"(c[3])
                 : "r"(a[0]), "r"(a[1]), "r"(a[2]), "r"(a[3]), "r"(b0), "r"(b1));
}
__device__ __forceinline__ float dot16(const float4 q[4], const float4* kr) {
    float4 k0 = kr[0], k1 = kr[1], k2 = kr[2], k3 = kr[3];
    float d = q[0].x*k0.x;
    d = fmaf(q[0].y, k0.y, d); d = fmaf(q[0].z, k0.z, d); d = fmaf(q[0].w, k0.w, d);
    d = fmaf(q[1].x, k1.x, d); d = fmaf(q[1].y, k1.y, d);
    d = fmaf(q[1].z, k1.z, d); d = fmaf(q[1].w, k1.w, d);
    d = fmaf(q[2].x, k2.x, d); d = fmaf(q[2].y, k2.y, d);
    d = fmaf(q[2].z, k2.z, d); d = fmaf(q[2].w, k2.w, d);
    d = fmaf(q[3].x, k3.x, d); d = fmaf(q[3].y, k3.y, d);
    d = fmaf(q[3].z, k3.z, d); d = fmaf(q[3].w, k3.w, d);
    return d;
}

// ---------------- GEMM 64x64 with fused rmsnorm prologue (K=128) -----------
// C[r][n] = scale_r * sum_k (A+Aadd)[r][k] * wv[k] * B[k][n]  (then opt GELU)
template<bool GELU>
__global__ void gemm_rms_k(const float* __restrict__ A, const float* __restrict__ Aadd,
                           const float* __restrict__ wv, const float* __restrict__ B,
                           float* __restrict__ C, int Nn) {
    __shared__ float Ast[32*64];
    __shared__ float Bs [32*64];
    __shared__ float sscale[64];
    const int tid = threadIdx.x;
    const int bm = blockIdx.y, bn = blockIdx.x;
    const int warp = tid >> 5, lane = tid & 31;

    // per-row rms scale (warp per row, 8 rows per warp)
    for (int r8 = 0; r8 < 8; r8++) {
        int r = r8*8 + warp;
        float4 v = ((const float4*)(A + (size_t)(bm*64 + r)*128))[lane];
        if (Aadd) {
            float4 a = ((const float4*)(Aadd + (size_t)(bm*64 + r)*128))[lane];
            v.x += a.x; v.y += a.y; v.z += a.z; v.w += a.w;
        }
        float ss = v.x*v.x + v.y*v.y + v.z*v.z + v.w*v.w;
        #pragma unroll
        for (int off = 16; off; off >>= 1)
            ss += __shfl_xor_sync(0xffffffffu, ss, off);
        if (lane == 0) sscale[r] = rsqrtf(ss*(1.0f/128.0f) + 1e-5f);
    }

    const int tx = tid & 15, ty = tid >> 4;
    float acc[4][4] = {};
    for (int k0 = 0; k0 < 128; k0 += 32) {
        for (int u = tid; u < 512; u += 256) {
            int r = u >> 3, c4 = u & 7;
            float4 a = *(const float4*)&A[(size_t)(bm*64 + r)*128 + k0 + c4*4];
            if (Aadd) {
                float4 d = *(const float4*)&Aadd[(size_t)(bm*64 + r)*128 + k0 + c4*4];
                a.x += d.x; a.y += d.y; a.z += d.z; a.w += d.w;
            }
            Ast[(c4*4+0)*64 + r] = a.x; Ast[(c4*4+1)*64 + r] = a.y;
            Ast[(c4*4+2)*64 + r] = a.z; Ast[(c4*4+3)*64 + r] = a.w;
        }
        for (int u = tid; u < 512; u += 256) {
            int kk = u >> 4, n4 = u & 15;
            float wk = wv[k0 + kk];
            float4 b = *(const float4*)&B[(size_t)(k0+kk)*Nn + bn*64 + n4*4];
            b.x *= wk; b.y *= wk; b.z *= wk; b.w *= wk;
            *(float4*)&Bs[kk*64 + n4*4] = b;
        }
        __syncthreads();
        #pragma unroll
        for (int kk = 0; kk < 32; kk++) {
            float4 a4 = *(const float4*)&Ast[kk*64 + ty*4];
            float4 b4 = *(const float4*)&Bs [kk*64 + tx*4];
            float av[4] = {a4.x, a4.y, a4.z, a4.w};
            float bv[4] = {b4.x, b4.y, b4.z, b4.w};
            #pragma unroll
            for (int i = 0; i < 4; i++)
                #pragma unroll
                for (int j = 0; j < 4; j++)
                    acc[i][j] = fmaf(av[i], bv[j], acc[i][j]);
        }
        __syncthreads();
    }
    #pragma unroll
    for (int i = 0; i < 4; i++) {
        int r = bm*64 + ty*4 + i;
        float sc = sscale[ty*4 + i];
        #pragma unroll
        for (int j = 0; j < 4; j++) {
            int c = bn*64 + tx*4 + j;
            float v = acc[i][j] * sc;
            if (GELU) v = 0.5f * v * (1.0f + erff(v * 0.70710678118654752f));
            C[(size_t)r*Nn + c] = v;
        }
    }
}

// ---------------- GEMM 32x64 (proj: K=512, +Cadd) ---------------------------
__global__ void gemm32_k(const float* __restrict__ A, const float* __restrict__ B,
                         const float* __restrict__ Cadd, float* __restrict__ C,
                         int Nn, int K) {
    __shared__ float Ast[32*32];   // [k][m]
    __shared__ float Bs [32*64];   // [k][n]
    const int tid = threadIdx.x;
    const int bm = blockIdx.y, bn = blockIdx.x;
    const int tx = tid & 15, ty = tid >> 4;
    float acc[2][4] = {};
    for (int k0 = 0; k0 < K; k0 += 32) {
        {   // A: 32 rows x 8 float4, one chunk per thread
            int r = tid >> 3, c4 = tid & 7;
            float4 a = *(const float4*)&A[(size_t)(bm*32 + r)*K + k0 + c4*4];
            Ast[(c4*4+0)*32 + r] = a.x; Ast[(c4*4+1)*32 + r] = a.y;
            Ast[(c4*4+2)*32 + r] = a.z; Ast[(c4*4+3)*32 + r] = a.w;
        }
        for (int u = tid; u < 512; u += 256) {
            int kk = u >> 4, n4 = u & 15;
            *(float4*)&Bs[kk*64 + n4*4] =
                *(const float4*)&B[(size_t)(k0+kk)*Nn + bn*64 + n4*4];
        }
        __syncthreads();
        #pragma unroll
        for (int kk = 0; kk < 32; kk++) {
            float2 a2 = *(const float2*)&Ast[kk*32 + ty*2];
            float4 b4 = *(const float4*)&Bs [kk*64 + tx*4];
            float av[2] = {a2.x, a2.y};
            float bv[4] = {b4.x, b4.y, b4.z, b4.w};
            #pragma unroll
            for (int i = 0; i < 2; i++)
                #pragma unroll
                for (int j = 0; j < 4; j++)
                    acc[i][j] = fmaf(av[i], bv[j], acc[i][j]);
        }
        __syncthreads();
    }
    #pragma unroll
    for (int i = 0; i < 2; i++) {
        int r = bm*32 + ty*2 + i;
        #pragma unroll
        for (int j = 0; j < 4; j++) {
            int c = bn*64 + tx*4 + j;
            C[(size_t)r*Nn + c] = acc[i][j] + Cadd[(size_t)r*Nn + c];
        }
    }
}

// ---------------- PASS 1: e12 = e @ W_e (cp.async staged, bf16 3-term) ------
#define EP_SMEM (2*128*ESTR*4)

__global__ void __launch_bounds__(256, 1) eproj4_k(
    const float* __restrict__ e, const float* __restrict__ We,
    __half2* __restrict__ e12)
{
    extern __shared__ float sa[];                  // [2][128][ESTR]
    __shared__ uint2 sbh[8*2*32];
    __shared__ uint2 sbl[8*2*32];

    const int tid = threadIdx.x;
    const int warp = tid >> 5, lane = tid & 31;
    const int g = lane >> 2, t = lane & 3;

    if (warp == 0) {
        #pragma unroll
        for (int kk = 0; kk < 8; kk++) {
            int c0 = kk*16 + 4*t;
            #pragma unroll
            for (int nt = 0; nt < 2; nt++) {
                int n = nt*8 + g;
                int wcol = (n & 1)*Hv + (n >> 1);
                float w0 = We[(c0+0)*16 + wcol];
                float w1 = We[(c0+1)*16 + wcol];
                float w2 = We[(c0+2)*16 + wcol];
                float w3 = We[(c0+3)*16 + wcol];
                unsigned h01, l01, h23, l23;
                bf_split(w0, w1, h01, l01);
                bf_split(w2, w3, h23, l23);
                sbh[(kk*2+nt)*32 + lane] = make_uint2(h01, h23);
                sbl[(kk*2+nt)*32 + lane] = make_uint2(l01, l23);
            }
        }
    }
    __syncthreads();

    auto load_tile = [&](int tile, int par) {
        const float* src = e + (size_t)tile*128*Dv;
        float* dst = sa + par*128*ESTR;
        #pragma unroll
        for (int ph = 0; ph < 16; ph++) {
            int u = tid + ph*256;
            int r = u >> 5, x4 = u & 31;
            cpa16(dst + r*ESTR + x4*4, src + (size_t)r*Dv + x4*4);
        }
    };

    int tile = blockIdx.x;
    load_tile(tile, 0);
    cp_commit();
    int par = 0;
    for (; tile < P1_NT; tile += gridDim.x) {
        int nxt = tile + gridDim.x;
        if (nxt < P1_NT) load_tile(nxt, par ^ 1);
        cp_commit();
        cp_wait1();
        __syncthreads();

        const float* A = sa + par*128*ESTR + warp*16*ESTR;
        float c[2][4] = {};
        #pragma unroll
        for (int kk = 0; kk < 8; kk++) {
            float4 r0 = *(const float4*)(A + (size_t) g    *ESTR + kk*16 + t*4);
            float4 r1 = *(const float4*)(A + (size_t)(g+8)*ESTR + kk*16 + t*4);
            unsigned ah[4], al[4];
            bf_split(r0.x, r0.y, ah[0], al[0]);
            bf_split(r1.x, r1.y, ah[1], al[1]);
            bf_split(r0.z, r0.w, ah[2], al[2]);
            bf_split(r1.z, r1.w, ah[3], al[3]);
            #pragma unroll
            for (int nt = 0; nt < 2; nt++) {
                uint2 bh = sbh[(kk*2+nt)*32 + lane];
                uint2 bl = sbl[(kk*2+nt)*32 + lane];
                mma_bf16(c[nt], ah, bh.x, bh.y);
                mma_bf16(c[nt], al, bh.x, bh.y);
                mma_bf16(c[nt], ah, bl.x, bl.y);
            }
        }
        // store as half2 (e1,e2) per (row, h): h = nt*4 + t
        __half2* out = e12 + ((size_t)tile*128 + warp*16)*8;
        #pragma unroll
        for (int nt = 0; nt < 2; nt++) {
            out[(size_t) g    *8 + nt*4 + t] = __floats2half2_rn(c[nt][0], c[nt][1]);
            out[(size_t)(g+8)*8 + nt*4 + t] = __floats2half2_rn(c[nt][2], c[nt][3]);
        }
        __syncthreads();
        par ^= 1;
    }
}

// ---------------- PASS 2: attention (2 i rows + full head frag per thread) --
#define ATTN_SMEM (2*2*64*KSTR*4)   // 132 KB

__global__ void __launch_bounds__(512, 1) attn4_k(
    const float* __restrict__ qkv, const __half2* __restrict__ e12,
    float* __restrict__ yout)
{
    extern __shared__ float sm[];
    float* ks = sm;                  // [2][64][KSTR]
    float* vs = sm + 2*64*KSTR;

    const int tid = threadIdx.x;
    const int b  = blockIdx.x >> 5;
    const int i0 = (blockIdx.x & 31) * 16;
    const int w = tid >> 5, lane = tid & 31;
    const int ip = w & 7, jh = w >> 3;
    const int hh = lane >> 2, jp = lane & 3;
    const int ia = i0 + ip*2, ib = ia + 1;

    float4 qa[4], qb[4];
    #pragma unroll
    for (int u = 0; u < 4; u++) {
        float4 q = *(const float4*)(qkv + (size_t)(b*Nv + ia)*384 + hh*16 + u*4);
        qa[u] = make_float4(q.x*0.25f, q.y*0.25f, q.z*0.25f, q.w*0.25f);
        q = *(const float4*)(qkv + (size_t)(b*Nv + ib)*384 + hh*16 + u*4);
        qb[u] = make_float4(q.x*0.25f, q.y*0.25f, q.z*0.25f, q.w*0.25f);
    }

    auto load_tile = [&](int t, int par) {
        #pragma unroll
        for (int ph = 0; ph < 4; ph++) {
            int u = tid + ph*512;
            int r = u >> 5, x4 = u & 31;
            int jg = (r < 32) ? (t*32 + r) : (256 + t*32 + (r - 32));
            const float* src = qkv + (size_t)(b*Nv + jg)*384 + 128 + x4*4;
            cpa16(ks + par*64*KSTR + r*KSTR + x4*4, src);
            cpa16(vs + par*64*KSTR + r*KSTR + x4*4, src + 128);
        }
    };

    float4 aA[4] = {}, aB[4] = {};
    float dA = 0.f, dB = 0.f;

    load_tile(0, 0);
    cp_commit();
    for (int t = 0; t < 8; t++) {
        int par = t & 1;
        if (t + 1 < 8) load_tile(t + 1, par ^ 1);
        cp_commit();
        cp_wait1();
        __syncthreads();

        const float* kt = ks + par*64*KSTR + jh*32*KSTR;
        const float* vt = vs + par*64*KSTR + jh*32*KSTR;
        const __half2* eA = e12 + ((size_t)(b*Nv + ia)*Nv + jh*256 + t*32)*8 + hh;
        const __half2* eB = eA + (size_t)Nv*8;
        #pragma unroll
        for (int jj = 0; jj < 8; jj++) {
            int l = jj*4 + jp;
            const float4* kr = (const float4*)(kt + l*KSTR + hh*16);
            float da = dot16(qa, kr);
            float db = dot16(qb, kr);
            float2 eea = __half22float2(eA[(size_t)l*8]);
            float2 eeb = __half22float2(eB[(size_t)l*8]);
            float pa = __expf(da + eea.x);
            float pb = __expf(db + eeb.x);
            dA += pa; dB += pb;
            pa *= eea.y; pb *= eeb.y;
            const float4* vr = (const float4*)(vt + l*KSTR + hh*16);
            #pragma unroll
            for (int u = 0; u < 4; u++) {
                float4 vv = vr[u];
                aA[u].x = fmaf(pa, vv.x, aA[u].x);
                aA[u].y = fmaf(pa, vv.y, aA[u].y);
                aA[u].z = fmaf(pa, vv.z, aA[u].z);
                aA[u].w = fmaf(pa, vv.w, aA[u].w);
                aB[u].x = fmaf(pb, vv.x, aB[u].x);
                aB[u].y = fmaf(pb, vv.y, aB[u].y);
                aB[u].z = fmaf(pb, vv.z, aB[u].z);
                aB[u].w = fmaf(pb, vv.w, aB[u].w);
            }
        }
        __syncthreads();
    }

    #pragma unroll
    for (int s = 1; s <= 2; s <<= 1) {
        dA += __shfl_xor_sync(0xffffffffu, dA, s);
        dB += __shfl_xor_sync(0xffffffffu, dB, s);
        #pragma unroll
        for (int u = 0; u < 4; u++) {
            aA[u].x += __shfl_xor_sync(0xffffffffu, aA[u].x, s);
            aA[u].y += __shfl_xor_sync(0xffffffffu, aA[u].y, s);
            aA[u].z += __shfl_xor_sync(0xffffffffu, aA[u].z, s);
            aA[u].w += __shfl_xor_sync(0xffffffffu, aA[u].w, s);
            aB[u].x += __shfl_xor_sync(0xffffffffu, aB[u].x, s);
            aB[u].y += __shfl_xor_sync(0xffffffffu, aB[u].y, s);
            aB[u].z += __shfl_xor_sync(0xffffffffu, aB[u].z, s);
            aB[u].w += __shfl_xor_sync(0xffffffffu, aB[u].w, s);
        }
    }

    float* xb = sm;
    float* xd = sm + 16*8*16;
    __syncthreads();
    if (jh == 1) {
        float* pa = xb + ((ip*2 + 0)*8 + hh)*16;
        float* pb = xb + ((ip*2 + 1)*8 + hh)*16;
        *(float4*)(pa + jp*4) = aA[jp];
        *(float4*)(pb + jp*4) = aB[jp];
        if (jp == 0) {
            xd[(ip*2 + 0)*8 + hh] = dA;
            xd[(ip*2 + 1)*8 + hh] = dB;
        }
    }
    __syncthreads();
    if (jh == 0) {
        const float* pa = xb + ((ip*2 + 0)*8 + hh)*16;
        const float* pb = xb + ((ip*2 + 1)*8 + hh)*16;
        float4 oa = *(const float4*)(pa + jp*4);
        float4 ob = *(const float4*)(pb + jp*4);
        float invA = 1.0f / (dA + xd[(ip*2 + 0)*8 + hh]);
        float invB = 1.0f / (dB + xd[(ip*2 + 1)*8 + hh]);
        float4 ra = make_float4((aA[jp].x + oa.x)*invA, (aA[jp].y + oa.y)*invA,
                                (aA[jp].z + oa.z)*invA, (aA[jp].w + oa.w)*invA);
        float4 rb = make_float4((aB[jp].x + ob.x)*invB, (aB[jp].y + ob.y)*invB,
                                (aB[jp].z + ob.z)*invB, (aB[jp].w + ob.w)*invB);
        *(float4*)(yout + (size_t)(b*Nv + ia)*Dv + hh*16 + jp*4) = ra;
        *(float4*)(yout + (size_t)(b*Nv + ib)*Dv + hh*16 + jp*4) = rb;
    }
}

// ---------------- host launch ----------------------------------------------
extern "C" void kernel_launch(void* const* d_in, const int* in_sizes, int n_in,
                              void* d_out, int out_size) {
    const float* h    = (const float*)d_in[0];
    const float* e    = (const float*)d_in[1];
    const float* W_h  = (const float*)d_in[2];
    const float* W_e  = (const float*)d_in[3];
    const float* n1   = (const float*)d_in[4];
    const float* n2   = (const float*)d_in[5];
    const float* W_fc = (const float*)d_in[6];
    const float* W_pr = (const float*)d_in[7];
    float* out = (float*)d_out;

    float *p_qkv, *p_y, *p_hid;
    __half2* p_e12;
    cudaGetSymbolAddress((void**)&p_qkv, g_qkv);
    cudaGetSymbolAddress((void**)&p_y,   g_y);
    cudaGetSymbolAddress((void**)&p_hid, g_hid);
    cudaGetSymbolAddress((void**)&p_e12, g_e12);

    cudaFuncSetAttribute(attn4_k, cudaFuncAttributeMaxDynamicSharedMemorySize,
                         ATTN_SMEM);
    cudaFuncSetAttribute(eproj4_k, cudaFuncAttributeMaxDynamicSharedMemorySize,
                         EP_SMEM);

    // 1) qkv = rmsnorm(h) @ W_h   (rms fused)
    gemm_rms_k<false><<<dim3(384/64, ROWS/64), 256>>>(h, nullptr, n1, W_h,
                                                      p_qkv, 3*Dv);
    // 2) e12 = e @ W_e  (fp16 out)
    eproj4_k<<<EPROJ_GRID, 256, EP_SMEM>>>(e, W_e, p_e12);
    // 3) attention -> y
    attn4_k<<<Bv*(Nv/16), 512, ATTN_SMEM>>>(p_qkv, p_e12, p_y);
    // 4) hid = gelu(rmsnorm(y + h) @ W_fc)   (rms fused)
    gemm_rms_k<true><<<dim3(FFv/64, ROWS/64), 256>>>(p_y, h, n2, W_fc,
                                                     p_hid, FFv);
    // 5) out = hid @ W_proj + y
    gemm32_k<<<dim3(Dv/64, ROWS/32), 256>>>(p_hid, W_pr, p_y, out, Dv, FFv);
}

// round 15
// speedup vs baseline: 2.0272x; 1.0325x over previous
#include <cuda_runtime.h>
#include <cuda_fp16.h>
#include <cstdint>

#define Bv   4
#define Nv   512
#define Dv   128
#define Hv   8
#define FFv  512
#define ROWS (Bv*Nv)
#define P1_NT 8192              // e tiles of 128 rows
#define KSTR 132                // padded k/v smem row stride (floats, attn)
#define ESTR 144                // padded e smem row stride (floats, eproj)
#define EPROJ_GRID 148

__device__ float   g_qkv[ROWS*3*Dv];
__device__ float   g_y  [ROWS*Dv];
__device__ float   g_hid[ROWS*FFv];
__device__ __half2 g_e12[(size_t)ROWS*Nv*8];   // 32 MB [b,i,j][h] = (e1,e2)

__device__ __forceinline__ void cpa16(void* s, const void* g) {
    unsigned sa = (unsigned)__cvta_generic_to_shared(s);
    asm volatile("cp.async.cg.shared.global [%0], [%1], 16;" :: "r"(sa), "l"(g));
}
__device__ __forceinline__ void cp_commit() { asm volatile("cp.async.commit_group;"); }
__device__ __forceinline__ void cp_wait1()  { asm volatile("cp.async.wait_group 1;" ::: "memory"); }

__device__ __forceinline__ unsigned pack_bf(float hi, float lo) {
    unsigned r;
    asm("cvt.rn.bf16x2.f32 %0, %1, %2;" : "=r"(r) : "f"(hi), "f"(lo));
    return r;
}
__device__ __forceinline__ void bf_split(float x0, float x1,
                                         unsigned& hi, unsigned& lo) {
    hi = pack_bf(x1, x0);
    float h0 = __uint_as_float(hi << 16);
    float h1 = __uint_as_float(hi & 0xffff0000u);
    lo = pack_bf(x1 - h1, x0 - h0);
}
__device__ __forceinline__ void mma_bf16(float c[4], const unsigned a[4],
                                         unsigned b0, unsigned b1) {
    asm volatile("mma.sync.aligned.m16n8k16.row.col.f32.bf16.bf16.f32 "
                 "{%0,%1,%2,%3},{%4,%5,%6,%7},{%8,%9},{%0,%1,%2,%3};"
                 : "+f"(c[0]), "+f"(c[1]), "+f"(c[2]), "+f"(c[3])
                 : "r"(a[0]), "r"(a[1]), "r"(a[2]), "r"(a[3]), "r"(b0), "r"(b1));
}
__device__ __forceinline__ float dot16(const float4 q[4], const float4* kr) {
    float4 k0 = kr[0], k1 = kr[1], k2 = kr[2], k3 = kr[3];
    float d = q[0].x*k0.x;
    d = fmaf(q[0].y, k0.y, d); d = fmaf(q[0].z, k0.z, d); d = fmaf(q[0].w, k0.w, d);
    d = fmaf(q[1].x, k1.x, d); d = fmaf(q[1].y, k1.y, d);
    d = fmaf(q[1].z, k1.z, d); d = fmaf(q[1].w, k1.w, d);
    d = fmaf(q[2].x, k2.x, d); d = fmaf(q[2].y, k2.y, d);
    d = fmaf(q[2].z, k2.z, d); d = fmaf(q[2].w, k2.w, d);
    d = fmaf(q[3].x, k3.x, d); d = fmaf(q[3].y, k3.y, d);
    d = fmaf(q[3].z, k3.z, d); d = fmaf(q[3].w, k3.w, d);
    return d;
}

// ---- GEMM + fused rmsnorm: 128 thr, tile 32x64, 4x4/thread (K=128) --------
// C[r][n] = GELU?( scale_r * sum_k (A+Aadd)[r][k]*wv[k]*B[k][n] )
template<bool GELU>
__global__ void __launch_bounds__(128) gemm_rms_k(
    const float* __restrict__ A, const float* __restrict__ Aadd,
    const float* __restrict__ wv, const float* __restrict__ B,
    float* __restrict__ C, int Nn) {
    __shared__ float Ast[32*36];    // [row][k] padded
    __shared__ float Bs [32*64];    // [k][n]
    __shared__ float sscale[32];
    const int tid = threadIdx.x;
    const int warp = tid >> 5, lane = tid & 31;
    const int bm = blockIdx.y, bn = blockIdx.x;

    // rms scale: warp per 8 rows
    for (int r8 = 0; r8 < 8; r8++) {
        int r = warp*8 + r8;
        float4 v = ((const float4*)(A + (size_t)(bm*32 + r)*128))[lane];
        if (Aadd) {
            float4 a = ((const float4*)(Aadd + (size_t)(bm*32 + r)*128))[lane];
            v.x += a.x; v.y += a.y; v.z += a.z; v.w += a.w;
        }
        float ss = v.x*v.x + v.y*v.y + v.z*v.z + v.w*v.w;
        #pragma unroll
        for (int off = 16; off; off >>= 1)
            ss += __shfl_xor_sync(0xffffffffu, ss, off);
        if (lane == 0) sscale[r] = rsqrtf(ss*(1.0f/128.0f) + 1e-5f);
    }
    __syncthreads();

    const int tx = tid & 15, ty = tid >> 4;   // tx 0..15 (n), ty 0..7 (m)
    float acc[4][4] = {};
    for (int k0 = 0; k0 < 128; k0 += 32) {
        #pragma unroll
        for (int u = tid; u < 256; u += 128) {          // A: 32 rows x 8 float4
            int r = u >> 3, c4 = u & 7;
            float4 a = *(const float4*)&A[(size_t)(bm*32 + r)*128 + k0 + c4*4];
            if (Aadd) {
                float4 d = *(const float4*)&Aadd[(size_t)(bm*32 + r)*128 + k0 + c4*4];
                a.x += d.x; a.y += d.y; a.z += d.z; a.w += d.w;
            }
            float sc = sscale[r];
            a.x *= sc; a.y *= sc; a.z *= sc; a.w *= sc;
            *(float4*)&Ast[r*36 + c4*4] = a;
        }
        #pragma unroll
        for (int u = tid; u < 512; u += 128) {          // B: 32 k x 16 float4
            int kk = u >> 4, n4 = u & 15;
            float wk = wv[k0 + kk];
            float4 b = *(const float4*)&B[(size_t)(k0+kk)*Nn + bn*64 + n4*4];
            b.x *= wk; b.y *= wk; b.z *= wk; b.w *= wk;
            *(float4*)&Bs[kk*64 + n4*4] = b;
        }
        __syncthreads();
        #pragma unroll
        for (int kk = 0; kk < 32; kk++) {
            float a0 = Ast[(ty*4+0)*36 + kk];
            float a1 = Ast[(ty*4+1)*36 + kk];
            float a2 = Ast[(ty*4+2)*36 + kk];
            float a3 = Ast[(ty*4+3)*36 + kk];
            float4 b4 = *(const float4*)&Bs[kk*64 + tx*4];
            float av[4] = {a0, a1, a2, a3};
            float bv[4] = {b4.x, b4.y, b4.z, b4.w};
            #pragma unroll
            for (int i = 0; i < 4; i++)
                #pragma unroll
                for (int j = 0; j < 4; j++)
                    acc[i][j] = fmaf(av[i], bv[j], acc[i][j]);
        }
        __syncthreads();
    }
    #pragma unroll
    for (int i = 0; i < 4; i++) {
        int r = bm*32 + ty*4 + i;
        #pragma unroll
        for (int j = 0; j < 4; j++) {
            int c = bn*64 + tx*4 + j;
            float v = acc[i][j];
            if (GELU) v = 0.5f * v * (1.0f + erff(v * 0.70710678118654752f));
            C[(size_t)r*Nn + c] = v;
        }
    }
}

// ---------------- GEMM 32x64 (proj: K=512, +Cadd), 256 threads --------------
__global__ void gemm32_k(const float* __restrict__ A, const float* __restrict__ B,
                         const float* __restrict__ Cadd, float* __restrict__ C,
                         int Nn, int K) {
    __shared__ float Ast[32*32];
    __shared__ float Bs [32*64];
    const int tid = threadIdx.x;
    const int bm = blockIdx.y, bn = blockIdx.x;
    const int tx = tid & 15, ty = tid >> 4;
    float acc[2][4] = {};
    for (int k0 = 0; k0 < K; k0 += 32) {
        {
            int r = tid >> 3, c4 = tid & 7;
            float4 a = *(const float4*)&A[(size_t)(bm*32 + r)*K + k0 + c4*4];
            Ast[(c4*4+0)*32 + r] = a.x; Ast[(c4*4+1)*32 + r] = a.y;
            Ast[(c4*4+2)*32 + r] = a.z; Ast[(c4*4+3)*32 + r] = a.w;
        }
        for (int u = tid; u < 512; u += 256) {
            int kk = u >> 4, n4 = u & 15;
            *(float4*)&Bs[kk*64 + n4*4] =
                *(const float4*)&B[(size_t)(k0+kk)*Nn + bn*64 + n4*4];
        }
        __syncthreads();
        #pragma unroll
        for (int kk = 0; kk < 32; kk++) {
            float2 a2 = *(const float2*)&Ast[kk*32 + ty*2];
            float4 b4 = *(const float4*)&Bs [kk*64 + tx*4];
            float av[2] = {a2.x, a2.y};
            float bv[4] = {b4.x, b4.y, b4.z, b4.w};
            #pragma unroll
            for (int i = 0; i < 2; i++)
                #pragma unroll
                for (int j = 0; j < 4; j++)
                    acc[i][j] = fmaf(av[i], bv[j], acc[i][j]);
        }
        __syncthreads();
    }
    #pragma unroll
    for (int i = 0; i < 2; i++) {
        int r = bm*32 + ty*2 + i;
        #pragma unroll
        for (int j = 0; j < 4; j++) {
            int c = bn*64 + tx*4 + j;
            C[(size_t)r*Nn + c] = acc[i][j] + Cadd[(size_t)r*Nn + c];
        }
    }
}

// ---------------- PASS 1: e12 = e @ W_e (cp.async staged, bf16 3-term) ------
#define EP_SMEM (2*128*ESTR*4)

__global__ void __launch_bounds__(256, 1) eproj4_k(
    const float* __restrict__ e, const float* __restrict__ We,
    __half2* __restrict__ e12)
{
    extern __shared__ float sa[];                  // [2][128][ESTR]
    __shared__ uint2 sbh[8*2*32];
    __shared__ uint2 sbl[8*2*32];

    const int tid = threadIdx.x;
    const int warp = tid >> 5, lane = tid & 31;
    const int g = lane >> 2, t = lane & 3;

    if (warp == 0) {
        #pragma unroll
        for (int kk = 0; kk < 8; kk++) {
            int c0 = kk*16 + 4*t;
            #pragma unroll
            for (int nt = 0; nt < 2; nt++) {
                int n = nt*8 + g;
                int wcol = (n & 1)*Hv + (n >> 1);
                float w0 = We[(c0+0)*16 + wcol];
                float w1 = We[(c0+1)*16 + wcol];
                float w2 = We[(c0+2)*16 + wcol];
                float w3 = We[(c0+3)*16 + wcol];
                unsigned h01, l01, h23, l23;
                bf_split(w0, w1, h01, l01);
                bf_split(w2, w3, h23, l23);
                sbh[(kk*2+nt)*32 + lane] = make_uint2(h01, h23);
                sbl[(kk*2+nt)*32 + lane] = make_uint2(l01, l23);
            }
        }
    }
    __syncthreads();

    auto load_tile = [&](int tile, int par) {
        const float* src = e + (size_t)tile*128*Dv;
        float* dst = sa + par*128*ESTR;
        #pragma unroll
        for (int ph = 0; ph < 16; ph++) {
            int u = tid + ph*256;
            int r = u >> 5, x4 = u & 31;
            cpa16(dst + r*ESTR + x4*4, src + (size_t)r*Dv + x4*4);
        }
    };

    int tile = blockIdx.x;
    load_tile(tile, 0);
    cp_commit();
    int par = 0;
    for (; tile < P1_NT; tile += gridDim.x) {
        int nxt = tile + gridDim.x;
        if (nxt < P1_NT) load_tile(nxt, par ^ 1);
        cp_commit();
        cp_wait1();
        __syncthreads();

        const float* A = sa + par*128*ESTR + warp*16*ESTR;
        float c[2][4] = {};
        #pragma unroll
        for (int kk = 0; kk < 8; kk++) {
            float4 r0 = *(const float4*)(A + (size_t) g    *ESTR + kk*16 + t*4);
            float4 r1 = *(const float4*)(A + (size_t)(g+8)*ESTR + kk*16 + t*4);
            unsigned ah[4], al[4];
            bf_split(r0.x, r0.y, ah[0], al[0]);
            bf_split(r1.x, r1.y, ah[1], al[1]);
            bf_split(r0.z, r0.w, ah[2], al[2]);
            bf_split(r1.z, r1.w, ah[3], al[3]);
            #pragma unroll
            for (int nt = 0; nt < 2; nt++) {
                uint2 bh = sbh[(kk*2+nt)*32 + lane];
                uint2 bl = sbl[(kk*2+nt)*32 + lane];
                mma_bf16(c[nt], ah, bh.x, bh.y);
                mma_bf16(c[nt], al, bh.x, bh.y);
                mma_bf16(c[nt], ah, bl.x, bl.y);
            }
        }
        __half2* out = e12 + ((size_t)tile*128 + warp*16)*8;
        #pragma unroll
        for (int nt = 0; nt < 2; nt++) {
            out[(size_t) g    *8 + nt*4 + t] = __floats2half2_rn(c[nt][0], c[nt][1]);
            out[(size_t)(g+8)*8 + nt*4 + t] = __floats2half2_rn(c[nt][2], c[nt][3]);
        }
        __syncthreads();
        par ^= 1;
    }
}

// ---------------- PASS 2: attention (2 i rows + full head frag per thread) --
#define ATTN_SMEM (2*2*64*KSTR*4)   // 132 KB

__global__ void __launch_bounds__(512, 1) attn4_k(
    const float* __restrict__ qkv, const __half2* __restrict__ e12,
    float* __restrict__ yout)
{
    extern __shared__ float sm[];
    float* ks = sm;                  // [2][64][KSTR]
    float* vs = sm + 2*64*KSTR;

    const int tid = threadIdx.x;
    const int b  = blockIdx.x >> 5;
    const int i0 = (blockIdx.x & 31) * 16;
    const int w = tid >> 5, lane = tid & 31;
    const int ip = w & 7, jh = w >> 3;
    const int hh = lane >> 2, jp = lane & 3;
    const int ia = i0 + ip*2, ib = ia + 1;

    float4 qa[4], qb[4];
    #pragma unroll
    for (int u = 0; u < 4; u++) {
        float4 q = *(const float4*)(qkv + (size_t)(b*Nv + ia)*384 + hh*16 + u*4);
        qa[u] = make_float4(q.x*0.25f, q.y*0.25f, q.z*0.25f, q.w*0.25f);
        q = *(const float4*)(qkv + (size_t)(b*Nv + ib)*384 + hh*16 + u*4);
        qb[u] = make_float4(q.x*0.25f, q.y*0.25f, q.z*0.25f, q.w*0.25f);
    }

    auto load_tile = [&](int t, int par) {
        #pragma unroll
        for (int ph = 0; ph < 4; ph++) {
            int u = tid + ph*512;
            int r = u >> 5, x4 = u & 31;
            int jg = (r < 32) ? (t*32 + r) : (256 + t*32 + (r - 32));
            const float* src = qkv + (size_t)(b*Nv + jg)*384 + 128 + x4*4;
            cpa16(ks + par*64*KSTR + r*KSTR + x4*4, src);
            cpa16(vs + par*64*KSTR + r*KSTR + x4*4, src + 128);
        }
    };

    float4 aA[4] = {}, aB[4] = {};
    float dA = 0.f, dB = 0.f;

    load_tile(0, 0);
    cp_commit();
    for (int t = 0; t < 8; t++) {
        int par = t & 1;
        if (t + 1 < 8) load_tile(t + 1, par ^ 1);
        cp_commit();
        cp_wait1();
        __syncthreads();

        const float* kt = ks + par*64*KSTR + jh*32*KSTR;
        const float* vt = vs + par*64*KSTR + jh*32*KSTR;
        const __half2* eA = e12 + ((size_t)(b*Nv + ia)*Nv + jh*256 + t*32)*8 + hh;
        const __half2* eB = eA + (size_t)Nv*8;
        #pragma unroll
        for (int jj = 0; jj < 8; jj++) {
            int l = jj*4 + jp;
            const float4* kr = (const float4*)(kt + l*KSTR + hh*16);
            float da = dot16(qa, kr);
            float db = dot16(qb, kr);
            float2 eea = __half22float2(eA[(size_t)l*8]);
            float2 eeb = __half22float2(eB[(size_t)l*8]);
            float pa = __expf(da + eea.x);
            float pb = __expf(db + eeb.x);
            dA += pa; dB += pb;
            pa *= eea.y; pb *= eeb.y;
            const float4* vr = (const float4*)(vt + l*KSTR + hh*16);
            #pragma unroll
            for (int u = 0; u < 4; u++) {
                float4 vv = vr[u];
                aA[u].x = fmaf(pa, vv.x, aA[u].x);
                aA[u].y = fmaf(pa, vv.y, aA[u].y);
                aA[u].z = fmaf(pa, vv.z, aA[u].z);
                aA[u].w = fmaf(pa, vv.w, aA[u].w);
                aB[u].x = fmaf(pb, vv.x, aB[u].x);
                aB[u].y = fmaf(pb, vv.y, aB[u].y);
                aB[u].z = fmaf(pb, vv.z, aB[u].z);
                aB[u].w = fmaf(pb, vv.w, aB[u].w);
            }
        }
        __syncthreads();
    }

    #pragma unroll
    for (int s = 1; s <= 2; s <<= 1) {
        dA += __shfl_xor_sync(0xffffffffu, dA, s);
        dB += __shfl_xor_sync(0xffffffffu, dB, s);
        #pragma unroll
        for (int u = 0; u < 4; u++) {
            aA[u].x += __shfl_xor_sync(0xffffffffu, aA[u].x, s);
            aA[u].y += __shfl_xor_sync(0xffffffffu, aA[u].y, s);
            aA[u].z += __shfl_xor_sync(0xffffffffu, aA[u].z, s);
            aA[u].w += __shfl_xor_sync(0xffffffffu, aA[u].w, s);
            aB[u].x += __shfl_xor_sync(0xffffffffu, aB[u].x, s);
            aB[u].y += __shfl_xor_sync(0xffffffffu, aB[u].y, s);
            aB[u].z += __shfl_xor_sync(0xffffffffu, aB[u].z, s);
            aB[u].w += __shfl_xor_sync(0xffffffffu, aB[u].w, s);
        }
    }

    float* xb = sm;
    float* xd = sm + 16*8*16;
    __syncthreads();
    if (jh == 1) {
        float* pa = xb + ((ip*2 + 0)*8 + hh)*16;
        float* pb = xb + ((ip*2 + 1)*8 + hh)*16;
        *(float4*)(pa + jp*4) = aA[jp];
        *(float4*)(pb + jp*4) = aB[jp];
        if (jp == 0) {
            xd[(ip*2 + 0)*8 + hh] = dA;
            xd[(ip*2 + 1)*8 + hh] = dB;
        }
    }
    __syncthreads();
    if (jh == 0) {
        const float* pa = xb + ((ip*2 + 0)*8 + hh)*16;
        const float* pb = xb + ((ip*2 + 1)*8 + hh)*16;
        float4 oa = *(const float4*)(pa + jp*4);
        float4 ob = *(const float4*)(pb + jp*4);
        float invA = 1.0f / (dA + xd[(ip*2 + 0)*8 + hh]);
        float invB = 1.0f / (dB + xd[(ip*2 + 1)*8 + hh]);
        float4 ra = make_float4((aA[jp].x + oa.x)*invA, (aA[jp].y + oa.y)*invA,
                                (aA[jp].z + oa.z)*invA, (aA[jp].w + oa.w)*invA);
        float4 rb = make_float4((aB[jp].x + ob.x)*invB, (aB[jp].y + ob.y)*invB,
                                (aB[jp].z + ob.z)*invB, (aB[jp].w + ob.w)*invB);
        *(float4*)(yout + (size_t)(b*Nv + ia)*Dv + hh*16 + jp*4) = ra;
        *(float4*)(yout + (size_t)(b*Nv + ib)*Dv + hh*16 + jp*4) = rb;
    }
}

// ---------------- host launch ----------------------------------------------
extern "C" void kernel_launch(void* const* d_in, const int* in_sizes, int n_in,
                              void* d_out, int out_size) {
    const float* h    = (const float*)d_in[0];
    const float* e    = (const float*)d_in[1];
    const float* W_h  = (const float*)d_in[2];
    const float* W_e  = (const float*)d_in[3];
    const float* n1   = (const float*)d_in[4];
    const float* n2   = (const float*)d_in[5];
    const float* W_fc = (const float*)d_in[6];
    const float* W_pr = (const float*)d_in[7];
    float* out = (float*)d_out;

    float *p_qkv, *p_y, *p_hid;
    __half2* p_e12;
    cudaGetSymbolAddress((void**)&p_qkv, g_qkv);
    cudaGetSymbolAddress((void**)&p_y,   g_y);
    cudaGetSymbolAddress((void**)&p_hid, g_hid);
    cudaGetSymbolAddress((void**)&p_e12, g_e12);

    cudaFuncSetAttribute(attn4_k, cudaFuncAttributeMaxDynamicSharedMemorySize,
                         ATTN_SMEM);
    cudaFuncSetAttribute(eproj4_k, cudaFuncAttributeMaxDynamicSharedMemorySize,
                         EP_SMEM);

    // 1) qkv = rmsnorm(h) @ W_h   (rms fused)
    gemm_rms_k<false><<<dim3(384/64, ROWS/32), 128>>>(h, nullptr, n1, W_h,
                                                      p_qkv, 3*Dv);
    // 2) e12 = e @ W_e  (fp16 out)
    eproj4_k<<<EPROJ_GRID, 256, EP_SMEM>>>(e, W_e, p_e12);
    // 3) attention -> y
    attn4_k<<<Bv*(Nv/16), 512, ATTN_SMEM>>>(p_qkv, p_e12, p_y);
    // 4) hid = gelu(rmsnorm(y + h) @ W_fc)   (rms fused)
    gemm_rms_k<true><<<dim3(FFv/64, ROWS/32), 128>>>(p_y, h, n2, W_fc,
                                                     p_hid, FFv);
    // 5) out = hid @ W_proj + y
    gemm32_k<<<dim3(Dv/64, ROWS/32), 256>>>(p_hid, W_pr, p_y, out, Dv, FFv);
}